// round 1
// baseline (speedup 1.0000x reference)
#include <cuda_runtime.h>
#include <cuda_bf16.h>
#include <math.h>

// Problem constants
#define BB   2
#define SS   2048
#define DD   768
#define HH   12
#define VV   50257
#define FFD  3072
#define HDIM 64
#define NTOK (BB*SS)

// ---------------------------------------------------------------------------
// Scratch (static device globals -- no allocation allowed)
// ---------------------------------------------------------------------------
__device__ float g_x   [NTOK*DD];      // embeddings + pos enc
__device__ float g_qkv [NTOK*3*DD];    // qkv projection
__device__ float g_attn[NTOK*DD];      // attention output (head-major concat)
__device__ float g_mha [NTOK*DD];      // attn @ Wsum + b_o + x
__device__ float g_h1  [NTOK*DD];      // LN1 output
__device__ float g_ff  [NTOK*FFD];     // relu(h1 @ W_ff1 + b)
__device__ float g_ffo [NTOK*DD];      // ff @ W_ff2 + b + h1
__device__ float g_h2  [NTOK*DD];      // LN2 output
__device__ float g_wsum[DD*DD];        // sum_h W_o[h*D:(h+1)*D, :]

// ---------------------------------------------------------------------------
// Embedding + sinusoidal positional encoding
//   div[p,d] = p / 10000^(2d/D); even d -> sin, odd d -> cos
// ---------------------------------------------------------------------------
__global__ __launch_bounds__(256) void embed_k(const int* __restrict__ ids,
                                               const float* __restrict__ emb,
                                               float* __restrict__ x)
{
    int t = blockIdx.x;            // token index in [0, NTOK)
    int s = t % SS;                // sequence position
    int id = ids[t];
    const float* er = emb + (size_t)id * DD;
    float* xr = x + (size_t)t * DD;
    for (int d = threadIdx.x; d < DD; d += 256) {
        float ang = (float)s * powf(10000.0f, -2.0f * (float)d / (float)DD);
        float pe  = (d & 1) ? cosf(ang) : sinf(ang);
        xr[d] = er[d] + pe;
    }
}

// ---------------------------------------------------------------------------
// W_o block-sum:  Wsum[r,c] = sum_h W_o[h*D + r, c]
// ---------------------------------------------------------------------------
__global__ __launch_bounds__(256) void wo_sum_k(const float* __restrict__ Wo,
                                                float* __restrict__ Ws)
{
    int i = blockIdx.x * 256 + threadIdx.x;
    if (i >= DD * DD) return;
    int r = i / DD, c = i % DD;
    float s = 0.f;
#pragma unroll
    for (int h = 0; h < HH; h++)
        s += Wo[((size_t)(h * DD + r)) * DD + c];
    Ws[i] = s;
}

// ---------------------------------------------------------------------------
// SGEMM: C[M,N] = A[M,K] @ B[K,N]  (+bias +residual, optional relu)
// 128x128 block tile, BK=8, 256 threads, 8x8 per-thread tile.
// blockIdx.x -> M tile, blockIdx.y -> N tile (M-fastest scheduling keeps the
// in-flight B working set small for the huge vocab GEMM -> L2 reuse).
// mode bits: 1 = +bias[col], 2 = relu, 4 = +Res[row,col]
// ---------------------------------------------------------------------------
__global__ __launch_bounds__(256) void sgemm_k(const float* __restrict__ A,
                                               const float* __restrict__ B,
                                               const float* __restrict__ bias,
                                               const float* __restrict__ Res,
                                               float* __restrict__ C,
                                               int M, int N, int K, int mode)
{
    __shared__ float As[8][128];
    __shared__ float Bs[8][128];

    const int tid = threadIdx.x;
    const int tx = tid & 15;        // 0..15 -> N sub
    const int ty = tid >> 4;        // 0..15 -> M sub
    const int m0 = blockIdx.x * 128;
    const int n0 = blockIdx.y * 128;

    const int aRow = tid >> 1;          // 0..127
    const int aCol = (tid & 1) * 4;     // 0 or 4
    const int bRow = tid >> 5;          // 0..7
    const int bCol = (tid & 31) * 4;    // 0..124

    float acc[8][8];
#pragma unroll
    for (int i = 0; i < 8; i++)
#pragma unroll
        for (int j = 0; j < 8; j++) acc[i][j] = 0.f;

    const bool nvec = ((N & 3) == 0);

    for (int k0 = 0; k0 < K; k0 += 8) {
        // load A tile (transposed into smem): K assumed multiple of 8 & 4-aligned
        {
            int gr = m0 + aRow;
            float4 v = make_float4(0.f, 0.f, 0.f, 0.f);
            if (gr < M)
                v = *reinterpret_cast<const float4*>(A + (size_t)gr * K + k0 + aCol);
            As[aCol + 0][aRow] = v.x;
            As[aCol + 1][aRow] = v.y;
            As[aCol + 2][aRow] = v.z;
            As[aCol + 3][aRow] = v.w;
        }
        // load B tile
        {
            int gc = n0 + bCol;
            const float* bp = B + (size_t)(k0 + bRow) * N + gc;
            if (nvec && (gc + 3 < N)) {
                float4 v = *reinterpret_cast<const float4*>(bp);
                Bs[bRow][bCol + 0] = v.x;
                Bs[bRow][bCol + 1] = v.y;
                Bs[bRow][bCol + 2] = v.z;
                Bs[bRow][bCol + 3] = v.w;
            } else {
#pragma unroll
                for (int i = 0; i < 4; i++)
                    Bs[bRow][bCol + i] = (gc + i < N) ? bp[i] : 0.f;
            }
        }
        __syncthreads();

#pragma unroll
        for (int k = 0; k < 8; k++) {
            float ar[8], br[8];
            *reinterpret_cast<float4*>(&ar[0]) = *reinterpret_cast<const float4*>(&As[k][ty * 8]);
            *reinterpret_cast<float4*>(&ar[4]) = *reinterpret_cast<const float4*>(&As[k][ty * 8 + 4]);
            *reinterpret_cast<float4*>(&br[0]) = *reinterpret_cast<const float4*>(&Bs[k][tx * 8]);
            *reinterpret_cast<float4*>(&br[4]) = *reinterpret_cast<const float4*>(&Bs[k][tx * 8 + 4]);
#pragma unroll
            for (int i = 0; i < 8; i++)
#pragma unroll
                for (int j = 0; j < 8; j++)
                    acc[i][j] = fmaf(ar[i], br[j], acc[i][j]);
        }
        __syncthreads();
    }

    // epilogue
#pragma unroll
    for (int i = 0; i < 8; i++) {
        int row = m0 + ty * 8 + i;
        if (row >= M) continue;
#pragma unroll
        for (int j = 0; j < 8; j++) {
            int col = n0 + tx * 8 + j;
            if (col >= N) continue;
            float v = acc[i][j];
            if (mode & 1) v += bias[col];
            if (mode & 4) v += Res[(size_t)row * N + col];
            if (mode & 2) v = fmaxf(v, 0.f);
            C[(size_t)row * N + col] = v;
        }
    }
}

// ---------------------------------------------------------------------------
// Causal flash attention (fp32, online softmax).
// grid = (S/64, H, B); block = 64 threads; one thread per q row.
// qkv layout: [token, 3*D], q at +0, k at +D, v at +2D, head h -> h*64.
// Output: g_attn[token, h*64 + d]  (== transpose(0,2,1,3).reshape(B,S,D))
// ---------------------------------------------------------------------------
#define QB 64
#define KB 32
__global__ __launch_bounds__(64) void attn_k(const float* __restrict__ qkv,
                                             float* __restrict__ out)
{
    const int qb = blockIdx.x;
    const int h  = blockIdx.y;
    const int b  = blockIdx.z;
    const int qi = qb * QB + threadIdx.x;       // q position in sequence
    const int tok = b * SS + qi;
    const int TD = 3 * DD;

    float qreg[HDIM];
#pragma unroll
    for (int d = 0; d < HDIM; d++)
        qreg[d] = qkv[(size_t)tok * TD + h * HDIM + d];

    float o[HDIM];
#pragma unroll
    for (int d = 0; d < HDIM; d++) o[d] = 0.f;
    float m = -1e30f, l = 0.f;

    __shared__ float sK[KB][HDIM];
    __shared__ float sV[KB][HDIM];

    const int kend = qb * QB + QB;   // causal: only need k <= qi < kend
    for (int k0 = 0; k0 < kend; k0 += KB) {
        // cooperative load of K/V tile: iteration i loads row i, coalesced
        for (int idx = threadIdx.x; idx < KB * HDIM; idx += 64) {
            int r = idx >> 6;        // idx / 64
            int d = idx & 63;
            size_t base = (size_t)(b * SS + k0 + r) * TD + h * HDIM + d;
            sK[r][d] = qkv[base + DD];
            sV[r][d] = qkv[base + 2 * DD];
        }
        __syncthreads();

        float sc[KB];
        float mt = -1e30f;
#pragma unroll
        for (int j = 0; j < KB; j++) {
            float s = 0.f;
#pragma unroll
            for (int d = 0; d < HDIM; d++) s = fmaf(qreg[d], sK[j][d], s);
            s *= 0.125f;                       // 1/sqrt(64)
            if (k0 + j > qi) s = -1e30f;       // causal mask
            sc[j] = s;
            mt = fmaxf(mt, s);
        }
        float mnew = fmaxf(m, mt);
        float corr = __expf(m - mnew);
        l *= corr;
#pragma unroll
        for (int d = 0; d < HDIM; d++) o[d] *= corr;
#pragma unroll
        for (int j = 0; j < KB; j++) {
            float p = __expf(sc[j] - mnew);
            l += p;
#pragma unroll
            for (int d = 0; d < HDIM; d++) o[d] = fmaf(p, sV[j][d], o[d]);
        }
        m = mnew;
        __syncthreads();
    }

    float inv = 1.f / l;
#pragma unroll
    for (int d = 0; d < HDIM; d++)
        out[(size_t)tok * DD + h * HDIM + d] = o[d] * inv;
}

// ---------------------------------------------------------------------------
// LayerNorm over D=768 (biased variance, eps=1e-5). One CTA per token.
// ---------------------------------------------------------------------------
__global__ __launch_bounds__(256) void layernorm_k(const float* __restrict__ X,
                                                   const float* __restrict__ g,
                                                   const float* __restrict__ b,
                                                   float* __restrict__ Y)
{
    int t = blockIdx.x;
    const float* xr = X + (size_t)t * DD;
    float vals[3];
    float s = 0.f, s2 = 0.f;
#pragma unroll
    for (int i = 0; i < 3; i++) {
        float v = xr[threadIdx.x + i * 256];
        vals[i] = v;
        s += v; s2 += v * v;
    }
#pragma unroll
    for (int o = 16; o > 0; o >>= 1) {
        s  += __shfl_xor_sync(0xFFFFFFFFu, s,  o);
        s2 += __shfl_xor_sync(0xFFFFFFFFu, s2, o);
    }
    __shared__ float rs[8], rs2[8];
    int w = threadIdx.x >> 5;
    if ((threadIdx.x & 31) == 0) { rs[w] = s; rs2[w] = s2; }
    __syncthreads();
    if (threadIdx.x < 32) {
        s  = (threadIdx.x < 8) ? rs [threadIdx.x] : 0.f;
        s2 = (threadIdx.x < 8) ? rs2[threadIdx.x] : 0.f;
#pragma unroll
        for (int o = 4; o > 0; o >>= 1) {
            s  += __shfl_xor_sync(0xFFFFFFFFu, s,  o);
            s2 += __shfl_xor_sync(0xFFFFFFFFu, s2, o);
        }
        if (threadIdx.x == 0) { rs[0] = s; rs2[0] = s2; }
    }
    __syncthreads();
    float mean = rs[0] * (1.f / DD);
    float var  = rs2[0] * (1.f / DD) - mean * mean;
    float rstd = rsqrtf(var + 1e-5f);
#pragma unroll
    for (int i = 0; i < 3; i++) {
        int d = threadIdx.x + i * 256;
        Y[(size_t)t * DD + d] = (vals[i] - mean) * rstd * g[d] + b[d];
    }
}

// ---------------------------------------------------------------------------
// Launch
// ---------------------------------------------------------------------------
extern "C" void kernel_launch(void* const* d_in, const int* in_sizes, int n_in,
                              void* d_out, int out_size)
{
    const int*   ids    = (const int*)  d_in[0];
    const float* emb    = (const float*)d_in[1];
    const float* W_qkv  = (const float*)d_in[2];
    const float* b_qkv  = (const float*)d_in[3];
    const float* W_o    = (const float*)d_in[4];
    const float* b_o    = (const float*)d_in[5];
    const float* ln1_g  = (const float*)d_in[6];
    const float* ln1_b  = (const float*)d_in[7];
    const float* W_ff1  = (const float*)d_in[8];
    const float* b_ff1  = (const float*)d_in[9];
    const float* W_ff2  = (const float*)d_in[10];
    const float* b_ff2  = (const float*)d_in[11];
    const float* ln2_g  = (const float*)d_in[12];
    const float* ln2_b  = (const float*)d_in[13];
    const float* W_out  = (const float*)d_in[14];
    const float* b_out  = (const float*)d_in[15];
    float* out = (float*)d_out;

    float *px, *pqkv, *pattn, *pmha, *ph1, *pff, *pffo, *ph2, *pws;
    cudaGetSymbolAddress((void**)&px,   g_x);
    cudaGetSymbolAddress((void**)&pqkv, g_qkv);
    cudaGetSymbolAddress((void**)&pattn,g_attn);
    cudaGetSymbolAddress((void**)&pmha, g_mha);
    cudaGetSymbolAddress((void**)&ph1,  g_h1);
    cudaGetSymbolAddress((void**)&pff,  g_ff);
    cudaGetSymbolAddress((void**)&pffo, g_ffo);
    cudaGetSymbolAddress((void**)&ph2,  g_h2);
    cudaGetSymbolAddress((void**)&pws,  g_wsum);

    // 1. embeddings + positional encoding
    embed_k<<<NTOK, 256>>>(ids, emb, px);

    // 2. QKV projection: [4096,768] @ [768,2304] + b
    sgemm_k<<<dim3(NTOK/128, (3*DD)/128), 256>>>(px, W_qkv, b_qkv, nullptr,
                                                 pqkv, NTOK, 3*DD, DD, 1);

    // 3. causal flash attention
    attn_k<<<dim3(SS/QB, HH, BB), 64>>>(pqkv, pattn);

    // 4. W_o head-block sum (tile() trick)
    wo_sum_k<<<(DD*DD + 255)/256, 256>>>(W_o, pws);

    // 5. mha = attn @ Wsum + b_o + x
    sgemm_k<<<dim3(NTOK/128, DD/128), 256>>>(pattn, pws, b_o, px,
                                             pmha, NTOK, DD, DD, 1|4);

    // 6. h1 = LN1(mha)
    layernorm_k<<<NTOK, 256>>>(pmha, ln1_g, ln1_b, ph1);

    // 7. ff = relu(h1 @ W_ff1 + b)
    sgemm_k<<<dim3(NTOK/128, FFD/128), 256>>>(ph1, W_ff1, b_ff1, nullptr,
                                              pff, NTOK, FFD, DD, 1|2);

    // 8. ffo = ff @ W_ff2 + b + h1
    sgemm_k<<<dim3(NTOK/128, DD/128), 256>>>(pff, W_ff2, b_ff2, ph1,
                                             pffo, NTOK, DD, FFD, 1|4);

    // 9. h2 = LN2(ffo)
    layernorm_k<<<NTOK, 256>>>(pffo, ln2_g, ln2_b, ph2);

    // 10. logits = h2 @ W_out + b_out   (the big one: N=50257)
    sgemm_k<<<dim3(NTOK/128, (VV + 127)/128), 256>>>(ph2, W_out, b_out, nullptr,
                                                     out, NTOK, VV, DD, 1);
}

// round 3
// speedup vs baseline: 2.0767x; 2.0767x over previous
#include <cuda_runtime.h>
#include <cuda_bf16.h>
#include <math.h>
#include <stdint.h>

// Problem constants
#define BB   2
#define SS   2048
#define DD   768
#define HH   12
#define VV   50257
#define FFD  3072
#define HDIM 64
#define NTOK (BB*SS)

// ---------------------------------------------------------------------------
// Scratch (static device globals -- no allocation allowed)
// ---------------------------------------------------------------------------
__device__ float g_x   [NTOK*DD];
__device__ float g_qkv [NTOK*3*DD];
__device__ float g_attn[NTOK*DD];
__device__ float g_mha [NTOK*DD];
__device__ float g_h1  [NTOK*DD];
__device__ float g_ff  [NTOK*FFD];
__device__ float g_ffo [NTOK*DD];
__device__ float g_h2  [NTOK*DD];

// bf16 hi/lo splits of activations (A operands)
__device__ __nv_bfloat16 g_xh [NTOK*DD],  g_xl [NTOK*DD];
__device__ __nv_bfloat16 g_ath[NTOK*DD],  g_atl[NTOK*DD];
__device__ __nv_bfloat16 g_h1h[NTOK*DD],  g_h1l[NTOK*DD];
__device__ __nv_bfloat16 g_ffh[NTOK*FFD], g_ffl[NTOK*FFD];
__device__ __nv_bfloat16 g_h2h[NTOK*DD],  g_h2l[NTOK*DD];

// bf16 hi/lo transposed weights [N,K]
__device__ __nv_bfloat16 g_wqkvTh[3*DD*DD],          g_wqkvTl[3*DD*DD];
__device__ __nv_bfloat16 g_wsumTh[DD*DD],            g_wsumTl[DD*DD];
__device__ __nv_bfloat16 g_wff1Th[(size_t)FFD*DD],   g_wff1Tl[(size_t)FFD*DD];
__device__ __nv_bfloat16 g_wff2Th[(size_t)DD*FFD],   g_wff2Tl[(size_t)DD*FFD];
__device__ __nv_bfloat16 g_woutTh[(size_t)VV*DD],    g_woutTl[(size_t)VV*DD];

// ---------------------------------------------------------------------------
// PTX helpers (plain sm_103-safe: cp.async, ldmatrix, mma.sync only)
// ---------------------------------------------------------------------------
__device__ __forceinline__ uint32_t smem_u32(const void* p) {
    uint32_t a;
    asm("{ .reg .u64 t; cvta.to.shared.u64 t, %1; cvt.u32.u64 %0, t; }"
        : "=r"(a) : "l"(p));
    return a;
}

#define CP16(dst, src) \
    asm volatile("cp.async.cg.shared.global [%0], [%1], 16;" \
                 :: "r"(dst), "l"(src) : "memory")
#define CP_COMMIT() asm volatile("cp.async.commit_group;" ::: "memory")
#define CP_WAIT1()  asm volatile("cp.async.wait_group 1;"  ::: "memory")
#define CP_WAIT0()  asm volatile("cp.async.wait_group 0;"  ::: "memory")

#define LDSM4(r, a) \
    asm volatile("ldmatrix.sync.aligned.m8n8.x4.shared.b16 {%0,%1,%2,%3}, [%4];" \
        : "=r"((r)[0]), "=r"((r)[1]), "=r"((r)[2]), "=r"((r)[3]) : "r"(a))

#define MMA(d, a, b0, b1) \
    asm volatile("mma.sync.aligned.m16n8k16.row.col.f32.bf16.bf16.f32 " \
        "{%0,%1,%2,%3}, {%4,%5,%6,%7}, {%8,%9}, {%0,%1,%2,%3};" \
        : "+f"((d)[0]), "+f"((d)[1]), "+f"((d)[2]), "+f"((d)[3]) \
        : "r"((a)[0]), "r"((a)[1]), "r"((a)[2]), "r"((a)[3]), \
          "r"(b0), "r"(b1))

// ---------------------------------------------------------------------------
// bf16 mma.sync GEMM: C[M,N] = A[M,K] @ Bt[N,K]^T   (3-term bf16 hi/lo split)
// CTA 128x128, 8 warps (2m x 4n), warp tile 64x32, BK=32, cp.async dbl-buffer.
// SMEM row stride 80B (pad) -> conflict-free ldmatrix.
// mode bits: 1=+bias[col], 2=relu, 4=+Res[row,col]
// ---------------------------------------------------------------------------
#define SMS   80                        // smem row stride bytes (32 bf16 + pad)
#define MOFF  10240                     // 128*80 per matrix
#define BUFSZ 40960                     // Ah,Al,Bh,Bl
#define TGSM  (2*BUFSZ)                 // 81920

__global__ __launch_bounds__(256, 1) void tgemm_k(
    const uint4* __restrict__ Ah, const uint4* __restrict__ Al,
    const uint4* __restrict__ Bh, const uint4* __restrict__ Bl,
    const float* __restrict__ bias, const float* __restrict__ Res,
    float* __restrict__ C, int M, int N, int K, int mode)
{
    extern __shared__ char sm[];
    const uint32_t sb = smem_u32(sm);
    const int tid  = threadIdx.x;
    const int lane = tid & 31;
    const int warp = tid >> 5;
    const int wm = warp >> 2;          // 0..1
    const int wn = warp & 3;           // 0..3
    const int m0 = blockIdx.x * 128;
    const int n0 = blockIdx.y * 128;

    const int Kv  = K >> 3;            // uint4 per gmem row
    const int nch = K >> 5;            // 32-wide K chunks

    const int lrow = tid >> 2;         // 0..63 (load row base, x2 iters)
    const int lseg = tid & 3;          // 0..3

    // accumulators: [m-tile][n-tile][4]
    float acc[4][4][4];
#pragma unroll
    for (int i = 0; i < 4; i++)
#pragma unroll
        for (int j = 0; j < 4; j++)
#pragma unroll
            for (int k = 0; k < 4; k++) acc[i][j][k] = 0.f;

    // ---- chunk loader (cp.async) ----
    auto load_chunk = [&](int c) {
        const int b = c & 1;
        const uint32_t base = sb + b * BUFSZ;
        const int kc4 = c << 2;
#pragma unroll
        for (int it = 0; it < 2; it++) {
            int row = lrow + it * 64;
            uint32_t d = base + row * SMS + lseg * 16;
            size_t ga = (size_t)(m0 + row) * Kv + kc4 + lseg;
            CP16(d,            Ah + ga);
            CP16(d + MOFF,     Al + ga);
            int rn = n0 + row; if (rn >= N) rn = N - 1;
            size_t gb = (size_t)rn * Kv + kc4 + lseg;
            CP16(d + 2*MOFF,   Bh + gb);
            CP16(d + 3*MOFF,   Bl + gb);
        }
        CP_COMMIT();
    };

    load_chunk(0);

    for (int c = 0; c < nch; c++) {
        if (c + 1 < nch) { load_chunk(c + 1); CP_WAIT1(); }
        else             { CP_WAIT0(); }
        __syncthreads();

        const uint32_t base = sb + (c & 1) * BUFSZ;
        const uint32_t ab = base + (wm * 64 + (lane & 15)) * SMS + ((lane >> 4) << 4);
        const uint32_t bb = base + 2*MOFF + (wn * 32 + (lane & 15)) * SMS + ((lane >> 4) << 4);

#pragma unroll
        for (int ks = 0; ks < 2; ks++) {
            const uint32_t ko = ks << 5;  // 16 bf16 = 32B
            uint32_t ahf[16], alf[16], bhf[8], blf[8];
#pragma unroll
            for (int mt = 0; mt < 4; mt++) {
                LDSM4(&ahf[mt*4], ab + mt * (16*SMS) + ko);
                LDSM4(&alf[mt*4], ab + MOFF + mt * (16*SMS) + ko);
            }
#pragma unroll
            for (int q = 0; q < 2; q++) {
                LDSM4(&bhf[q*4], bb + q * (16*SMS) + ko);
                LDSM4(&blf[q*4], bb + MOFF + q * (16*SMS) + ko);
            }
#pragma unroll
            for (int mt = 0; mt < 4; mt++)
#pragma unroll
                for (int nt = 0; nt < 4; nt++) {
                    const int q = (nt >> 1) * 4, r = nt & 1;
                    MMA(acc[mt][nt], &ahf[mt*4], bhf[q+r], bhf[q+2+r]);
                    MMA(acc[mt][nt], &alf[mt*4], bhf[q+r], bhf[q+2+r]);
                    MMA(acc[mt][nt], &ahf[mt*4], blf[q+r], blf[q+2+r]);
                }
        }
        __syncthreads();
    }

    // ---- epilogue: regs -> C with fused bias/residual/relu ----
#pragma unroll
    for (int mt = 0; mt < 4; mt++) {
        const int row0 = m0 + wm * 64 + mt * 16 + (lane >> 2);
#pragma unroll
        for (int nt = 0; nt < 4; nt++) {
            const int col = n0 + wn * 32 + nt * 8 + ((lane & 3) << 1);
            if (col >= N) continue;
            const float* d = acc[mt][nt];
#pragma unroll
            for (int h = 0; h < 2; h++) {
                const int r = row0 + h * 8;
                size_t o = (size_t)r * N + col;
                float x0 = d[h*2+0];
                if (mode & 1) x0 += bias[col];
                if (mode & 4) x0 += Res[o];
                if (mode & 2) x0 = fmaxf(x0, 0.f);
                C[o] = x0;
                if (col + 1 < N) {
                    float x1 = d[h*2+1];
                    if (mode & 1) x1 += bias[col+1];
                    if (mode & 4) x1 += Res[o+1];
                    if (mode & 2) x1 = fmaxf(x1, 0.f);
                    C[o+1] = x1;
                }
            }
        }
    }
}

// ---------------------------------------------------------------------------
// Embedding + positional encoding
// ---------------------------------------------------------------------------
__global__ __launch_bounds__(256) void embed_k(const int* __restrict__ ids,
                                               const float* __restrict__ emb,
                                               float* __restrict__ x)
{
    int t = blockIdx.x;
    int s = t % SS;
    int id = ids[t];
    const float* er = emb + (size_t)id * DD;
    float* xr = x + (size_t)t * DD;
    for (int d = threadIdx.x; d < DD; d += 256) {
        float ang = (float)s * powf(10000.0f, -2.0f * (float)d / (float)DD);
        float pe  = (d & 1) ? cosf(ang) : sinf(ang);
        xr[d] = er[d] + pe;
    }
}

// ---------------------------------------------------------------------------
// Activation split: fp32 -> bf16 hi/lo (vectorized)
// ---------------------------------------------------------------------------
__global__ __launch_bounds__(256) void asplit_k(const float4* __restrict__ X,
                                                uint2* __restrict__ Xh,
                                                uint2* __restrict__ Xl, int n4)
{
    int i = blockIdx.x * 256 + threadIdx.x;
    if (i >= n4) return;
    float4 v = X[i];
    float vv[4] = {v.x, v.y, v.z, v.w};
    __nv_bfloat16 h[4], l[4];
#pragma unroll
    for (int j = 0; j < 4; j++) {
        h[j] = __float2bfloat16(vv[j]);
        l[j] = __float2bfloat16(vv[j] - __bfloat162float(h[j]));
    }
    Xh[i] = *(uint2*)h;
    Xl[i] = *(uint2*)l;
}

// ---------------------------------------------------------------------------
// Weight transpose + split: W[K,N] -> Th/Tl[N,K] bf16
// ---------------------------------------------------------------------------
__global__ __launch_bounds__(256) void wsplitT_k(const float* __restrict__ W,
                                                 __nv_bfloat16* __restrict__ Th,
                                                 __nv_bfloat16* __restrict__ Tl,
                                                 int K, int N)
{
    __shared__ float t[32][33];
    int k0 = blockIdx.y * 32, n0 = blockIdx.x * 32;
    int tx = threadIdx.x & 31, ty = threadIdx.x >> 5;
#pragma unroll
    for (int i = 0; i < 4; i++) {
        int k = k0 + ty + i * 8, n = n0 + tx;
        t[ty + i * 8][tx] = (k < K && n < N) ? W[(size_t)k * N + n] : 0.f;
    }
    __syncthreads();
#pragma unroll
    for (int i = 0; i < 4; i++) {
        int n = n0 + ty + i * 8, k = k0 + tx;
        if (n < N && k < K) {
            float v = t[tx][ty + i * 8];
            __nv_bfloat16 h = __float2bfloat16(v);
            Th[(size_t)n * K + k] = h;
            Tl[(size_t)n * K + k] = __float2bfloat16(v - __bfloat162float(h));
        }
    }
}

// ---------------------------------------------------------------------------
// W_o head-block sum + transpose + split: T[c,r] = sum_h Wo[h*D+r, c]
// ---------------------------------------------------------------------------
__global__ __launch_bounds__(256) void wosumT_k(const float* __restrict__ Wo,
                                                __nv_bfloat16* __restrict__ Th,
                                                __nv_bfloat16* __restrict__ Tl)
{
    __shared__ float t[32][33];
    int r0 = blockIdx.y * 32, c0 = blockIdx.x * 32;
    int tx = threadIdx.x & 31, ty = threadIdx.x >> 5;
#pragma unroll
    for (int i = 0; i < 4; i++) {
        int r = r0 + ty + i * 8;
        float s = 0.f;
#pragma unroll
        for (int h = 0; h < HH; h++)
            s += Wo[((size_t)(h * DD + r)) * DD + c0 + tx];
        t[ty + i * 8][tx] = s;
    }
    __syncthreads();
#pragma unroll
    for (int i = 0; i < 4; i++) {
        int cc = c0 + ty + i * 8;
        int rr = r0 + tx;
        float v = t[tx][ty + i * 8];
        __nv_bfloat16 h = __float2bfloat16(v);
        Th[(size_t)cc * DD + rr] = h;
        Tl[(size_t)cc * DD + rr] = __float2bfloat16(v - __bfloat162float(h));
    }
}

// ---------------------------------------------------------------------------
// Causal flash attention (fp32, online softmax)
// ---------------------------------------------------------------------------
#define QB 64
#define KB 32
__global__ __launch_bounds__(64) void attn_k(const float* __restrict__ qkv,
                                             float* __restrict__ out)
{
    const int qb = blockIdx.x;
    const int h  = blockIdx.y;
    const int b  = blockIdx.z;
    const int qi = qb * QB + threadIdx.x;
    const int tok = b * SS + qi;
    const int TD = 3 * DD;

    float qreg[HDIM];
#pragma unroll
    for (int d = 0; d < HDIM; d++)
        qreg[d] = qkv[(size_t)tok * TD + h * HDIM + d];

    float o[HDIM];
#pragma unroll
    for (int d = 0; d < HDIM; d++) o[d] = 0.f;
    float m = -1e30f, l = 0.f;

    __shared__ float sK[KB][HDIM];
    __shared__ float sV[KB][HDIM];

    const int kend = qb * QB + QB;
    for (int k0 = 0; k0 < kend; k0 += KB) {
        for (int idx = threadIdx.x; idx < KB * HDIM; idx += 64) {
            int r = idx >> 6;
            int d = idx & 63;
            size_t base = (size_t)(b * SS + k0 + r) * TD + h * HDIM + d;
            sK[r][d] = qkv[base + DD];
            sV[r][d] = qkv[base + 2 * DD];
        }
        __syncthreads();

        float sc[KB];
        float mt = -1e30f;
#pragma unroll
        for (int j = 0; j < KB; j++) {
            float s = 0.f;
#pragma unroll
            for (int d = 0; d < HDIM; d++) s = fmaf(qreg[d], sK[j][d], s);
            s *= 0.125f;
            if (k0 + j > qi) s = -1e30f;
            sc[j] = s;
            mt = fmaxf(mt, s);
        }
        float mnew = fmaxf(m, mt);
        float corr = __expf(m - mnew);
        l *= corr;
#pragma unroll
        for (int d = 0; d < HDIM; d++) o[d] *= corr;
#pragma unroll
        for (int j = 0; j < KB; j++) {
            float p = __expf(sc[j] - mnew);
            l += p;
#pragma unroll
            for (int d = 0; d < HDIM; d++) o[d] = fmaf(p, sV[j][d], o[d]);
        }
        m = mnew;
        __syncthreads();
    }

    float inv = 1.f / l;
#pragma unroll
    for (int d = 0; d < HDIM; d++)
        out[(size_t)tok * DD + h * HDIM + d] = o[d] * inv;
}

// ---------------------------------------------------------------------------
// LayerNorm over D=768
// ---------------------------------------------------------------------------
__global__ __launch_bounds__(256) void layernorm_k(const float* __restrict__ X,
                                                   const float* __restrict__ g,
                                                   const float* __restrict__ b,
                                                   float* __restrict__ Y)
{
    int t = blockIdx.x;
    const float* xr = X + (size_t)t * DD;
    float vals[3];
    float s = 0.f, s2 = 0.f;
#pragma unroll
    for (int i = 0; i < 3; i++) {
        float v = xr[threadIdx.x + i * 256];
        vals[i] = v;
        s += v; s2 += v * v;
    }
#pragma unroll
    for (int o = 16; o > 0; o >>= 1) {
        s  += __shfl_xor_sync(0xFFFFFFFFu, s,  o);
        s2 += __shfl_xor_sync(0xFFFFFFFFu, s2, o);
    }
    __shared__ float rs[8], rs2[8];
    int w = threadIdx.x >> 5;
    if ((threadIdx.x & 31) == 0) { rs[w] = s; rs2[w] = s2; }
    __syncthreads();
    if (threadIdx.x < 32) {
        s  = (threadIdx.x < 8) ? rs [threadIdx.x] : 0.f;
        s2 = (threadIdx.x < 8) ? rs2[threadIdx.x] : 0.f;
#pragma unroll
        for (int o = 4; o > 0; o >>= 1) {
            s  += __shfl_xor_sync(0xFFFFFFFFu, s,  o);
            s2 += __shfl_xor_sync(0xFFFFFFFFu, s2, o);
        }
        if (threadIdx.x == 0) { rs[0] = s; rs2[0] = s2; }
    }
    __syncthreads();
    float mean = rs[0] * (1.f / DD);
    float var  = rs2[0] * (1.f / DD) - mean * mean;
    float rstd = rsqrtf(var + 1e-5f);
#pragma unroll
    for (int i = 0; i < 3; i++) {
        int d = threadIdx.x + i * 256;
        Y[(size_t)t * DD + d] = (vals[i] - mean) * rstd * g[d] + b[d];
    }
}

// ---------------------------------------------------------------------------
// Launch
// ---------------------------------------------------------------------------
static inline void run_gemm(const __nv_bfloat16* Ah, const __nv_bfloat16* Al,
                            const __nv_bfloat16* Bh, const __nv_bfloat16* Bl,
                            const float* bias, const float* Res, float* C,
                            int M, int N, int K, int mode)
{
    dim3 grid(M / 128, (N + 127) / 128);
    tgemm_k<<<grid, 256, TGSM>>>((const uint4*)Ah, (const uint4*)Al,
                                 (const uint4*)Bh, (const uint4*)Bl,
                                 bias, Res, C, M, N, K, mode);
}

extern "C" void kernel_launch(void* const* d_in, const int* in_sizes, int n_in,
                              void* d_out, int out_size)
{
    const int*   ids    = (const int*)  d_in[0];
    const float* emb    = (const float*)d_in[1];
    const float* W_qkv  = (const float*)d_in[2];
    const float* b_qkv  = (const float*)d_in[3];
    const float* W_o    = (const float*)d_in[4];
    const float* b_o    = (const float*)d_in[5];
    const float* ln1_g  = (const float*)d_in[6];
    const float* ln1_b  = (const float*)d_in[7];
    const float* W_ff1  = (const float*)d_in[8];
    const float* b_ff1  = (const float*)d_in[9];
    const float* W_ff2  = (const float*)d_in[10];
    const float* b_ff2  = (const float*)d_in[11];
    const float* ln2_g  = (const float*)d_in[12];
    const float* ln2_b  = (const float*)d_in[13];
    const float* W_out  = (const float*)d_in[14];
    const float* b_out  = (const float*)d_in[15];
    float* out = (float*)d_out;

    cudaFuncSetAttribute(tgemm_k, cudaFuncAttributeMaxDynamicSharedMemorySize,
                         TGSM);

    float *px, *pqkv, *pattn, *pmha, *ph1, *pff, *pffo, *ph2;
    cudaGetSymbolAddress((void**)&px,   g_x);
    cudaGetSymbolAddress((void**)&pqkv, g_qkv);
    cudaGetSymbolAddress((void**)&pattn,g_attn);
    cudaGetSymbolAddress((void**)&pmha, g_mha);
    cudaGetSymbolAddress((void**)&ph1,  g_h1);
    cudaGetSymbolAddress((void**)&pff,  g_ff);
    cudaGetSymbolAddress((void**)&pffo, g_ffo);
    cudaGetSymbolAddress((void**)&ph2,  g_h2);

    __nv_bfloat16 *xh,*xl,*ath,*atl,*h1h,*h1l,*ffh,*ffl,*h2h,*h2l;
    cudaGetSymbolAddress((void**)&xh,  g_xh);  cudaGetSymbolAddress((void**)&xl,  g_xl);
    cudaGetSymbolAddress((void**)&ath, g_ath); cudaGetSymbolAddress((void**)&atl, g_atl);
    cudaGetSymbolAddress((void**)&h1h, g_h1h); cudaGetSymbolAddress((void**)&h1l, g_h1l);
    cudaGetSymbolAddress((void**)&ffh, g_ffh); cudaGetSymbolAddress((void**)&ffl, g_ffl);
    cudaGetSymbolAddress((void**)&h2h, g_h2h); cudaGetSymbolAddress((void**)&h2l, g_h2l);

    __nv_bfloat16 *wqh,*wql,*wsh,*wsl,*w1h,*w1l,*w2h,*w2l,*woh,*wol;
    cudaGetSymbolAddress((void**)&wqh, g_wqkvTh); cudaGetSymbolAddress((void**)&wql, g_wqkvTl);
    cudaGetSymbolAddress((void**)&wsh, g_wsumTh); cudaGetSymbolAddress((void**)&wsl, g_wsumTl);
    cudaGetSymbolAddress((void**)&w1h, g_wff1Th); cudaGetSymbolAddress((void**)&w1l, g_wff1Tl);
    cudaGetSymbolAddress((void**)&w2h, g_wff2Th); cudaGetSymbolAddress((void**)&w2l, g_wff2Tl);
    cudaGetSymbolAddress((void**)&woh, g_woutTh); cudaGetSymbolAddress((void**)&wol, g_woutTl);

    // Weight prep (independent of activations)
    wsplitT_k<<<dim3((3*DD + 31)/32, (DD + 31)/32), 256>>>(W_qkv, wqh, wql, DD, 3*DD);
    wosumT_k <<<dim3(DD/32, DD/32), 256>>>(W_o, wsh, wsl);
    wsplitT_k<<<dim3((FFD + 31)/32, (DD + 31)/32), 256>>>(W_ff1, w1h, w1l, DD, FFD);
    wsplitT_k<<<dim3((DD + 31)/32, (FFD + 31)/32), 256>>>(W_ff2, w2h, w2l, FFD, DD);
    wsplitT_k<<<dim3((VV + 31)/32, (DD + 31)/32), 256>>>(W_out, woh, wol, DD, VV);

    // 1. embeddings + PE, split
    embed_k<<<NTOK, 256>>>(ids, emb, px);
    asplit_k<<<(NTOK*DD/4 + 255)/256, 256>>>((const float4*)px, (uint2*)xh, (uint2*)xl, NTOK*DD/4);

    // 2. QKV projection
    run_gemm(xh, xl, wqh, wql, b_qkv, nullptr, pqkv, NTOK, 3*DD, DD, 1);

    // 3. attention
    attn_k<<<dim3(SS/QB, HH, BB), 64>>>(pqkv, pattn);
    asplit_k<<<(NTOK*DD/4 + 255)/256, 256>>>((const float4*)pattn, (uint2*)ath, (uint2*)atl, NTOK*DD/4);

    // 4. mha = attn @ Wsum + b_o + x
    run_gemm(ath, atl, wsh, wsl, b_o, px, pmha, NTOK, DD, DD, 1|4);

    // 5. LN1
    layernorm_k<<<NTOK, 256>>>(pmha, ln1_g, ln1_b, ph1);
    asplit_k<<<(NTOK*DD/4 + 255)/256, 256>>>((const float4*)ph1, (uint2*)h1h, (uint2*)h1l, NTOK*DD/4);

    // 6. FF1 + relu
    run_gemm(h1h, h1l, w1h, w1l, b_ff1, nullptr, pff, NTOK, FFD, DD, 1|2);
    asplit_k<<<(NTOK*FFD/4 + 255)/256, 256>>>((const float4*)pff, (uint2*)ffh, (uint2*)ffl, NTOK*FFD/4);

    // 7. FF2 + residual
    run_gemm(ffh, ffl, w2h, w2l, b_ff2, ph1, pffo, NTOK, DD, FFD, 1|4);

    // 8. LN2
    layernorm_k<<<NTOK, 256>>>(pffo, ln2_g, ln2_b, ph2);
    asplit_k<<<(NTOK*DD/4 + 255)/256, 256>>>((const float4*)ph2, (uint2*)h2h, (uint2*)h2l, NTOK*DD/4);

    // 9. vocab projection (the big one)
    run_gemm(h2h, h2l, woh, wol, b_out, nullptr, out, NTOK, VV, DD, 1);
}

// round 4
// speedup vs baseline: 2.9394x; 1.4154x over previous
#include <cuda_runtime.h>
#include <cuda_fp16.h>
#include <math.h>
#include <stdint.h>

// Problem constants
#define BB   2
#define SS   2048
#define DD   768
#define HH   12
#define VV   50257
#define FFD  3072
#define HDIM 64
#define NTOK (BB*SS)

// ---------------------------------------------------------------------------
// Scratch (static device globals -- no allocation allowed)
// ---------------------------------------------------------------------------
__device__ float g_x   [NTOK*DD];      // embeddings + PE (residual for step 4)
__device__ float g_qkv [NTOK*3*DD];    // qkv fp32 (attention input)
__device__ float g_mha [NTOK*DD];
__device__ float g_h1  [NTOK*DD];      // LN1 out fp32 (residual for step 7)
__device__ float g_ffo [NTOK*DD];

// fp16 hi/lo splits of activations (A operands)
__device__ __half g_xh [NTOK*DD],  g_xl [NTOK*DD];
__device__ __half g_ath[NTOK*DD],  g_atl[NTOK*DD];
__device__ __half g_h1h[NTOK*DD],  g_h1l[NTOK*DD];
__device__ __half g_ffh[NTOK*FFD], g_ffl[NTOK*FFD];
__device__ __half g_h2h[NTOK*DD],  g_h2l[NTOK*DD];

// fp16 transposed weights [N,K] (single precision-level: B-side unsplit)
__device__ __half g_wqkvT[3*DD*DD];
__device__ __half g_wsumT[DD*DD];
__device__ __half g_wff1T[(size_t)FFD*DD];
__device__ __half g_wff2T[(size_t)DD*FFD];
__device__ __half g_woutT[(size_t)VV*DD];

// ---------------------------------------------------------------------------
// PTX helpers (plain sm_103-safe: cp.async, ldmatrix, mma.sync only)
// ---------------------------------------------------------------------------
__device__ __forceinline__ uint32_t smem_u32(const void* p) {
    uint32_t a;
    asm("{ .reg .u64 t; cvta.to.shared.u64 t, %1; cvt.u32.u64 %0, t; }"
        : "=r"(a) : "l"(p));
    return a;
}

#define CP16(dst, src) \
    asm volatile("cp.async.cg.shared.global [%0], [%1], 16;" \
                 :: "r"(dst), "l"(src) : "memory")
#define CP_COMMIT() asm volatile("cp.async.commit_group;" ::: "memory")
#define CP_WAIT1()  asm volatile("cp.async.wait_group 1;"  ::: "memory")
#define CP_WAIT0()  asm volatile("cp.async.wait_group 0;"  ::: "memory")

#define LDSM4(r, a) \
    asm volatile("ldmatrix.sync.aligned.m8n8.x4.shared.b16 {%0,%1,%2,%3}, [%4];" \
        : "=r"((r)[0]), "=r"((r)[1]), "=r"((r)[2]), "=r"((r)[3]) : "r"(a))

#define MMAH(d, a, b0, b1) \
    asm volatile("mma.sync.aligned.m16n8k16.row.col.f32.f16.f16.f32 " \
        "{%0,%1,%2,%3}, {%4,%5,%6,%7}, {%8,%9}, {%0,%1,%2,%3};" \
        : "+f"((d)[0]), "+f"((d)[1]), "+f"((d)[2]), "+f"((d)[3]) \
        : "r"((a)[0]), "r"((a)[1]), "r"((a)[2]), "r"((a)[3]), \
          "r"(b0), "r"(b1))

__device__ __forceinline__ void split_store(float x, __half* H, __half* L, size_t o) {
    __half h = __float2half_rn(x);
    H[o] = h;
    L[o] = __float2half_rn(x - __half2float(h));
}

// ---------------------------------------------------------------------------
// fp16 mma.sync GEMM: C[M,N] = A[M,K] @ Bt[N,K]^T,  A = Ah + Al (exact),
// B single fp16.  2 MMAs per fragment pair.
// CTA 128x128, 8 warps (2m x 4n), warp tile 64x32, BK=32, cp.async dbl-buffer.
// SMEM row stride 80B -> conflict-free ldmatrix.
// mode: 1=+bias, 2=relu, 4=+Res.  Outputs: C fp32 (nullable) and/or Ch/Cl
// fp16 hi/lo split (nullable).
// ---------------------------------------------------------------------------
#define SMS   80
#define MOFF  10240                     // 128*80 per matrix
#define BUFSZ 30720                     // Ah, Al, B
#define TGSM  (2*BUFSZ)                 // 61440

__global__ __launch_bounds__(256, 1) void tgemm_k(
    const uint4* __restrict__ Ah, const uint4* __restrict__ Al,
    const uint4* __restrict__ Bt,
    const float* __restrict__ bias, const float* __restrict__ Res,
    float* __restrict__ C, __half* __restrict__ Ch, __half* __restrict__ Cl,
    int M, int N, int K, int mode)
{
    extern __shared__ char sm[];
    const uint32_t sb = smem_u32(sm);
    const int tid  = threadIdx.x;
    const int lane = tid & 31;
    const int warp = tid >> 5;
    const int wm = warp >> 2;
    const int wn = warp & 3;
    const int m0 = blockIdx.x * 128;
    const int n0 = blockIdx.y * 128;

    const int Kv  = K >> 3;
    const int nch = K >> 5;

    const int lrow = tid >> 2;
    const int lseg = tid & 3;

    float acc[4][4][4];
#pragma unroll
    for (int i = 0; i < 4; i++)
#pragma unroll
        for (int j = 0; j < 4; j++)
#pragma unroll
            for (int k = 0; k < 4; k++) acc[i][j][k] = 0.f;

    auto load_chunk = [&](int c) {
        const int b = c & 1;
        const uint32_t base = sb + b * BUFSZ;
        const int kc4 = c << 2;
#pragma unroll
        for (int it = 0; it < 2; it++) {
            int row = lrow + it * 64;
            uint32_t d = base + row * SMS + lseg * 16;
            size_t ga = (size_t)(m0 + row) * Kv + kc4 + lseg;
            CP16(d,          Ah + ga);
            CP16(d + MOFF,   Al + ga);
            int rn = n0 + row; if (rn >= N) rn = N - 1;
            size_t gb = (size_t)rn * Kv + kc4 + lseg;
            CP16(d + 2*MOFF, Bt + gb);
        }
        CP_COMMIT();
    };

    load_chunk(0);

    for (int c = 0; c < nch; c++) {
        if (c + 1 < nch) { load_chunk(c + 1); CP_WAIT1(); }
        else             { CP_WAIT0(); }
        __syncthreads();

        const uint32_t base = sb + (c & 1) * BUFSZ;
        const uint32_t ab = base + (wm * 64 + (lane & 15)) * SMS + ((lane >> 4) << 4);
        const uint32_t bb = base + 2*MOFF + (wn * 32 + (lane & 15)) * SMS + ((lane >> 4) << 4);

#pragma unroll
        for (int ks = 0; ks < 2; ks++) {
            const uint32_t ko = ks << 5;
            uint32_t ahf[16], alf[16], bf[8];
#pragma unroll
            for (int mt = 0; mt < 4; mt++) {
                LDSM4(&ahf[mt*4], ab + mt * (16*SMS) + ko);
                LDSM4(&alf[mt*4], ab + MOFF + mt * (16*SMS) + ko);
            }
#pragma unroll
            for (int q = 0; q < 2; q++)
                LDSM4(&bf[q*4], bb + q * (16*SMS) + ko);
#pragma unroll
            for (int mt = 0; mt < 4; mt++)
#pragma unroll
                for (int nt = 0; nt < 4; nt++) {
                    const int q = (nt >> 1) * 4, r = nt & 1;
                    MMAH(acc[mt][nt], &ahf[mt*4], bf[q+r], bf[q+2+r]);
                    MMAH(acc[mt][nt], &alf[mt*4], bf[q+r], bf[q+2+r]);
                }
        }
        __syncthreads();
    }

    // epilogue (fused bias / residual / relu, fp32 and/or split-fp16 outputs)
#pragma unroll
    for (int mt = 0; mt < 4; mt++) {
        const int row0 = m0 + wm * 64 + mt * 16 + (lane >> 2);
#pragma unroll
        for (int nt = 0; nt < 4; nt++) {
            const int col = n0 + wn * 32 + nt * 8 + ((lane & 3) << 1);
            if (col >= N) continue;
            const float* d = acc[mt][nt];
#pragma unroll
            for (int h = 0; h < 2; h++) {
                const int r = row0 + h * 8;
                size_t o = (size_t)r * N + col;
#pragma unroll
                for (int j = 0; j < 2; j++) {
                    if (col + j >= N) break;
                    float x = d[h*2+j];
                    if (mode & 1) x += bias[col+j];
                    if (mode & 4) x += Res[o+j];
                    if (mode & 2) x = fmaxf(x, 0.f);
                    if (C)  C[o+j] = x;
                    if (Ch) split_store(x, Ch, Cl, o+j);
                }
            }
        }
    }
}

// ---------------------------------------------------------------------------
// Embedding + positional encoding, with fused fp16 split
// ---------------------------------------------------------------------------
__global__ __launch_bounds__(256) void embed_k(const int* __restrict__ ids,
                                               const float* __restrict__ emb,
                                               float* __restrict__ x,
                                               __half* __restrict__ xh,
                                               __half* __restrict__ xl)
{
    int t = blockIdx.x;
    int s = t % SS;
    int id = ids[t];
    const float* er = emb + (size_t)id * DD;
    size_t base = (size_t)t * DD;
    for (int d = threadIdx.x; d < DD; d += 256) {
        float ang = (float)s * powf(10000.0f, -2.0f * (float)d / (float)DD);
        float pe  = (d & 1) ? cosf(ang) : sinf(ang);
        float v = er[d] + pe;
        x[base + d] = v;
        split_store(v, xh, xl, base + d);
    }
}

// ---------------------------------------------------------------------------
// Weight transpose + fp16 convert: W[K,N] -> T[N,K]
// ---------------------------------------------------------------------------
__global__ __launch_bounds__(256) void wconvT_k(const float* __restrict__ W,
                                                __half* __restrict__ T,
                                                int K, int N)
{
    __shared__ float t[32][33];
    int k0 = blockIdx.y * 32, n0 = blockIdx.x * 32;
    int tx = threadIdx.x & 31, ty = threadIdx.x >> 5;
#pragma unroll
    for (int i = 0; i < 4; i++) {
        int k = k0 + ty + i * 8, n = n0 + tx;
        t[ty + i * 8][tx] = (k < K && n < N) ? W[(size_t)k * N + n] : 0.f;
    }
    __syncthreads();
#pragma unroll
    for (int i = 0; i < 4; i++) {
        int n = n0 + ty + i * 8, k = k0 + tx;
        if (n < N && k < K)
            T[(size_t)n * K + k] = __float2half_rn(t[tx][ty + i * 8]);
    }
}

// ---------------------------------------------------------------------------
// W_o head-block sum + transpose + fp16: T[c,r] = fp16(sum_h Wo[h*D+r, c])
// ---------------------------------------------------------------------------
__global__ __launch_bounds__(256) void wosumT_k(const float* __restrict__ Wo,
                                                __half* __restrict__ T)
{
    __shared__ float t[32][33];
    int r0 = blockIdx.y * 32, c0 = blockIdx.x * 32;
    int tx = threadIdx.x & 31, ty = threadIdx.x >> 5;
#pragma unroll
    for (int i = 0; i < 4; i++) {
        int r = r0 + ty + i * 8;
        float s = 0.f;
#pragma unroll
        for (int h = 0; h < HH; h++)
            s += Wo[((size_t)(h * DD + r)) * DD + c0 + tx];
        t[ty + i * 8][tx] = s;
    }
    __syncthreads();
#pragma unroll
    for (int i = 0; i < 4; i++) {
        int cc = c0 + ty + i * 8;
        int rr = r0 + tx;
        T[(size_t)cc * DD + rr] = __float2half_rn(t[tx][ty + i * 8]);
    }
}

// ---------------------------------------------------------------------------
// Causal flash attention (fp32, online softmax), fused fp16-split epilogue
// ---------------------------------------------------------------------------
#define QB 64
#define KB 32
__global__ __launch_bounds__(64) void attn_k(const float* __restrict__ qkv,
                                             __half* __restrict__ oh,
                                             __half* __restrict__ ol)
{
    const int qb = blockIdx.x;
    const int h  = blockIdx.y;
    const int b  = blockIdx.z;
    const int qi = qb * QB + threadIdx.x;
    const int tok = b * SS + qi;
    const int TD = 3 * DD;

    float qreg[HDIM];
#pragma unroll
    for (int d = 0; d < HDIM; d++)
        qreg[d] = qkv[(size_t)tok * TD + h * HDIM + d];

    float o[HDIM];
#pragma unroll
    for (int d = 0; d < HDIM; d++) o[d] = 0.f;
    float m = -1e30f, l = 0.f;

    __shared__ float sK[KB][HDIM];
    __shared__ float sV[KB][HDIM];

    const int kend = qb * QB + QB;
    for (int k0 = 0; k0 < kend; k0 += KB) {
        for (int idx = threadIdx.x; idx < KB * HDIM; idx += 64) {
            int r = idx >> 6;
            int d = idx & 63;
            size_t base = (size_t)(b * SS + k0 + r) * TD + h * HDIM + d;
            sK[r][d] = qkv[base + DD];
            sV[r][d] = qkv[base + 2 * DD];
        }
        __syncthreads();

        float sc[KB];
        float mt = -1e30f;
#pragma unroll
        for (int j = 0; j < KB; j++) {
            float s = 0.f;
#pragma unroll
            for (int d = 0; d < HDIM; d++) s = fmaf(qreg[d], sK[j][d], s);
            s *= 0.125f;
            if (k0 + j > qi) s = -1e30f;
            sc[j] = s;
            mt = fmaxf(mt, s);
        }
        float mnew = fmaxf(m, mt);
        float corr = __expf(m - mnew);
        l *= corr;
#pragma unroll
        for (int d = 0; d < HDIM; d++) o[d] *= corr;
#pragma unroll
        for (int j = 0; j < KB; j++) {
            float p = __expf(sc[j] - mnew);
            l += p;
#pragma unroll
            for (int d = 0; d < HDIM; d++) o[d] = fmaf(p, sV[j][d], o[d]);
        }
        m = mnew;
        __syncthreads();
    }

    float inv = 1.f / l;
#pragma unroll
    for (int d = 0; d < HDIM; d++) {
        size_t idx = (size_t)tok * DD + h * HDIM + d;
        split_store(o[d] * inv, oh, ol, idx);
    }
}

// ---------------------------------------------------------------------------
// LayerNorm over D=768, optional fp32 out + optional fused fp16 split out
// ---------------------------------------------------------------------------
__global__ __launch_bounds__(256) void layernorm_k(const float* __restrict__ X,
                                                   const float* __restrict__ g,
                                                   const float* __restrict__ b,
                                                   float* __restrict__ Y,
                                                   __half* __restrict__ Yh,
                                                   __half* __restrict__ Yl)
{
    int t = blockIdx.x;
    const float* xr = X + (size_t)t * DD;
    float vals[3];
    float s = 0.f, s2 = 0.f;
#pragma unroll
    for (int i = 0; i < 3; i++) {
        float v = xr[threadIdx.x + i * 256];
        vals[i] = v;
        s += v; s2 += v * v;
    }
#pragma unroll
    for (int o = 16; o > 0; o >>= 1) {
        s  += __shfl_xor_sync(0xFFFFFFFFu, s,  o);
        s2 += __shfl_xor_sync(0xFFFFFFFFu, s2, o);
    }
    __shared__ float rs[8], rs2[8];
    int w = threadIdx.x >> 5;
    if ((threadIdx.x & 31) == 0) { rs[w] = s; rs2[w] = s2; }
    __syncthreads();
    if (threadIdx.x < 32) {
        s  = (threadIdx.x < 8) ? rs [threadIdx.x] : 0.f;
        s2 = (threadIdx.x < 8) ? rs2[threadIdx.x] : 0.f;
#pragma unroll
        for (int o = 4; o > 0; o >>= 1) {
            s  += __shfl_xor_sync(0xFFFFFFFFu, s,  o);
            s2 += __shfl_xor_sync(0xFFFFFFFFu, s2, o);
        }
        if (threadIdx.x == 0) { rs[0] = s; rs2[0] = s2; }
    }
    __syncthreads();
    float mean = rs[0] * (1.f / DD);
    float var  = rs2[0] * (1.f / DD) - mean * mean;
    float rstd = rsqrtf(var + 1e-5f);
#pragma unroll
    for (int i = 0; i < 3; i++) {
        int d = threadIdx.x + i * 256;
        float v = (vals[i] - mean) * rstd * g[d] + b[d];
        size_t o = (size_t)t * DD + d;
        if (Y)  Y[o] = v;
        if (Yh) split_store(v, Yh, Yl, o);
    }
}

// ---------------------------------------------------------------------------
// Launch
// ---------------------------------------------------------------------------
static inline void run_gemm(const __half* Ah, const __half* Al, const __half* Bt,
                            const float* bias, const float* Res,
                            float* C, __half* Ch, __half* Cl,
                            int M, int N, int K, int mode)
{
    dim3 grid(M / 128, (N + 127) / 128);
    tgemm_k<<<grid, 256, TGSM>>>((const uint4*)Ah, (const uint4*)Al,
                                 (const uint4*)Bt, bias, Res, C, Ch, Cl,
                                 M, N, K, mode);
}

extern "C" void kernel_launch(void* const* d_in, const int* in_sizes, int n_in,
                              void* d_out, int out_size)
{
    const int*   ids    = (const int*)  d_in[0];
    const float* emb    = (const float*)d_in[1];
    const float* W_qkv  = (const float*)d_in[2];
    const float* b_qkv  = (const float*)d_in[3];
    const float* W_o    = (const float*)d_in[4];
    const float* b_o    = (const float*)d_in[5];
    const float* ln1_g  = (const float*)d_in[6];
    const float* ln1_b  = (const float*)d_in[7];
    const float* W_ff1  = (const float*)d_in[8];
    const float* b_ff1  = (const float*)d_in[9];
    const float* W_ff2  = (const float*)d_in[10];
    const float* b_ff2  = (const float*)d_in[11];
    const float* ln2_g  = (const float*)d_in[12];
    const float* ln2_b  = (const float*)d_in[13];
    const float* W_out  = (const float*)d_in[14];
    const float* b_out  = (const float*)d_in[15];
    float* out = (float*)d_out;

    cudaFuncSetAttribute(tgemm_k, cudaFuncAttributeMaxDynamicSharedMemorySize,
                         TGSM);

    float *px, *pqkv, *pmha, *ph1, *pffo;
    cudaGetSymbolAddress((void**)&px,   g_x);
    cudaGetSymbolAddress((void**)&pqkv, g_qkv);
    cudaGetSymbolAddress((void**)&pmha, g_mha);
    cudaGetSymbolAddress((void**)&ph1,  g_h1);
    cudaGetSymbolAddress((void**)&pffo, g_ffo);

    __half *xh,*xl,*ath,*atl,*h1h,*h1l,*ffh,*ffl,*h2h,*h2l;
    cudaGetSymbolAddress((void**)&xh,  g_xh);  cudaGetSymbolAddress((void**)&xl,  g_xl);
    cudaGetSymbolAddress((void**)&ath, g_ath); cudaGetSymbolAddress((void**)&atl, g_atl);
    cudaGetSymbolAddress((void**)&h1h, g_h1h); cudaGetSymbolAddress((void**)&h1l, g_h1l);
    cudaGetSymbolAddress((void**)&ffh, g_ffh); cudaGetSymbolAddress((void**)&ffl, g_ffl);
    cudaGetSymbolAddress((void**)&h2h, g_h2h); cudaGetSymbolAddress((void**)&h2l, g_h2l);

    __half *wq,*ws,*w1,*w2,*wo;
    cudaGetSymbolAddress((void**)&wq, g_wqkvT);
    cudaGetSymbolAddress((void**)&ws, g_wsumT);
    cudaGetSymbolAddress((void**)&w1, g_wff1T);
    cudaGetSymbolAddress((void**)&w2, g_wff2T);
    cudaGetSymbolAddress((void**)&wo, g_woutT);

    // Weight prep
    wconvT_k<<<dim3((3*DD + 31)/32, (DD + 31)/32), 256>>>(W_qkv, wq, DD, 3*DD);
    wosumT_k<<<dim3(DD/32, DD/32), 256>>>(W_o, ws);
    wconvT_k<<<dim3((FFD + 31)/32, (DD + 31)/32), 256>>>(W_ff1, w1, DD, FFD);
    wconvT_k<<<dim3((DD + 31)/32, (FFD + 31)/32), 256>>>(W_ff2, w2, FFD, DD);
    wconvT_k<<<dim3((VV + 31)/32, (DD + 31)/32), 256>>>(W_out, wo, DD, VV);

    // 1. embeddings + PE (fused split)
    embed_k<<<NTOK, 256>>>(ids, emb, px, xh, xl);

    // 2. QKV projection (fp32 out for attention)
    run_gemm(xh, xl, wq, b_qkv, nullptr, pqkv, nullptr, nullptr,
             NTOK, 3*DD, DD, 1);

    // 3. attention (fused split epilogue)
    attn_k<<<dim3(SS/QB, HH, BB), 64>>>(pqkv, ath, atl);

    // 4. mha = attn @ Wsum + b_o + x
    run_gemm(ath, atl, ws, b_o, px, pmha, nullptr, nullptr,
             NTOK, DD, DD, 1|4);

    // 5. LN1 (fp32 residual + split)
    layernorm_k<<<NTOK, 256>>>(pmha, ln1_g, ln1_b, ph1, h1h, h1l);

    // 6. FF1 + relu (split-only out)
    run_gemm(h1h, h1l, w1, b_ff1, nullptr, nullptr, ffh, ffl,
             NTOK, FFD, DD, 1|2);

    // 7. FF2 + residual (fp32 out)
    run_gemm(ffh, ffl, w2, b_ff2, ph1, pffo, nullptr, nullptr,
             NTOK, DD, FFD, 1|4);

    // 8. LN2 (split-only out)
    layernorm_k<<<NTOK, 256>>>(pffo, ln2_g, ln2_b, nullptr, h2h, h2l);

    // 9. vocab projection
    run_gemm(h2h, h2l, wo, b_out, nullptr, out, nullptr, nullptr,
             NTOK, VV, DD, 1);
}

// round 5
// speedup vs baseline: 3.6147x; 1.2297x over previous
#include <cuda_runtime.h>
#include <cuda_fp16.h>
#include <math.h>
#include <stdint.h>

// Problem constants
#define BB   2
#define SS   2048
#define DD   768
#define HH   12
#define VV   50257
#define FFD  3072
#define HDIM 64
#define NTOK (BB*SS)

// ---------------------------------------------------------------------------
// Scratch (static device globals -- no allocation allowed)
// ---------------------------------------------------------------------------
__device__ float g_x   [NTOK*DD];      // embeddings + PE (residual for step 4)
__device__ float g_qkv [NTOK*3*DD];    // qkv fp32 (attention input)
__device__ float g_mha [NTOK*DD];
__device__ float g_h1  [NTOK*DD];      // LN1 out fp32 (residual for step 7)
__device__ float g_ffo [NTOK*DD];

// fp16 hi/lo splits of activations (A operands)
__device__ __half g_xh [NTOK*DD],  g_xl [NTOK*DD];
__device__ __half g_ath[NTOK*DD],  g_atl[NTOK*DD];
__device__ __half g_h1h[NTOK*DD],  g_h1l[NTOK*DD];
__device__ __half g_ffh[NTOK*FFD], g_ffl[NTOK*FFD];
__device__ __half g_h2h[NTOK*DD],  g_h2l[NTOK*DD];

// fp16 transposed weights [N,K]
__device__ __half g_wqkvT[3*DD*DD];
__device__ __half g_wsumT[DD*DD];
__device__ __half g_wff1T[(size_t)FFD*DD];
__device__ __half g_wff2T[(size_t)DD*FFD];
__device__ __half g_woutT[(size_t)VV*DD];

// ---------------------------------------------------------------------------
// PTX helpers (plain sm_103-safe: cp.async, ldmatrix, mma.sync only)
// ---------------------------------------------------------------------------
__device__ __forceinline__ uint32_t smem_u32(const void* p) {
    uint32_t a;
    asm("{ .reg .u64 t; cvta.to.shared.u64 t, %1; cvt.u32.u64 %0, t; }"
        : "=r"(a) : "l"(p));
    return a;
}

#define CP16(dst, src) \
    asm volatile("cp.async.cg.shared.global [%0], [%1], 16;" \
                 :: "r"(dst), "l"(src) : "memory")
#define CP_COMMIT() asm volatile("cp.async.commit_group;" ::: "memory")
#define CP_WAIT1()  asm volatile("cp.async.wait_group 1;"  ::: "memory")
#define CP_WAIT0()  asm volatile("cp.async.wait_group 0;"  ::: "memory")

#define LDSM4(r, a) \
    asm volatile("ldmatrix.sync.aligned.m8n8.x4.shared.b16 {%0,%1,%2,%3}, [%4];" \
        : "=r"((r)[0]), "=r"((r)[1]), "=r"((r)[2]), "=r"((r)[3]) : "r"(a))

#define MMAH(d, a, b0, b1) \
    asm volatile("mma.sync.aligned.m16n8k16.row.col.f32.f16.f16.f32 " \
        "{%0,%1,%2,%3}, {%4,%5,%6,%7}, {%8,%9}, {%0,%1,%2,%3};" \
        : "+f"((d)[0]), "+f"((d)[1]), "+f"((d)[2]), "+f"((d)[3]) \
        : "r"((a)[0]), "r"((a)[1]), "r"((a)[2]), "r"((a)[3]), \
          "r"(b0), "r"(b1))

__device__ __forceinline__ void split_store(float x, __half* H, __half* L, size_t o) {
    __half h = __float2half_rn(x);
    H[o] = h;
    L[o] = __float2half_rn(x - __half2float(h));
}

// ---------------------------------------------------------------------------
// fp16 mma.sync GEMM: C[M,N] = A[M,K] @ Bt[N,K]^T
//   TWO_TERM=1: A = Ah + Al (exact fp32 reconstruction), 2 MMAs / frag pair
//   TWO_TERM=0: A = Ah single fp16, 1 MMA / frag pair  (vocab projection)
// CTA 128x128, 8 warps (2m x 4n), warp tile 64x32, BK=32, cp.async dbl-buffer.
// SMEM row stride 80B -> conflict-free ldmatrix.
// mode: 1=+bias, 2=relu, 4=+Res.  Outputs: C fp32 and/or Ch/Cl split (nullable)
// ---------------------------------------------------------------------------
#define SMS   80
#define MOFF  10240                     // 128*80 per matrix
#define BUFSZ 30720                     // Ah, Al, B slots
#define TGSM  (2*BUFSZ)                 // 61440

template<int TWO_TERM>
__global__ __launch_bounds__(256, 1) void tgemm_k(
    const uint4* __restrict__ Ah, const uint4* __restrict__ Al,
    const uint4* __restrict__ Bt,
    const float* __restrict__ bias, const float* __restrict__ Res,
    float* __restrict__ C, __half* __restrict__ Ch, __half* __restrict__ Cl,
    int M, int N, int K, int mode)
{
    extern __shared__ char sm[];
    const uint32_t sb = smem_u32(sm);
    const int tid  = threadIdx.x;
    const int lane = tid & 31;
    const int warp = tid >> 5;
    const int wm = warp >> 2;
    const int wn = warp & 3;
    const int m0 = blockIdx.x * 128;
    const int n0 = blockIdx.y * 128;

    const int Kv  = K >> 3;
    const int nch = K >> 5;

    const int lrow = tid >> 2;
    const int lseg = tid & 3;

    float acc[4][4][4];
#pragma unroll
    for (int i = 0; i < 4; i++)
#pragma unroll
        for (int j = 0; j < 4; j++)
#pragma unroll
            for (int k = 0; k < 4; k++) acc[i][j][k] = 0.f;

    auto load_chunk = [&](int c) {
        const int b = c & 1;
        const uint32_t base = sb + b * BUFSZ;
        const int kc4 = c << 2;
#pragma unroll
        for (int it = 0; it < 2; it++) {
            int row = lrow + it * 64;
            uint32_t d = base + row * SMS + lseg * 16;
            size_t ga = (size_t)(m0 + row) * Kv + kc4 + lseg;
            CP16(d,          Ah + ga);
            if (TWO_TERM) CP16(d + MOFF, Al + ga);
            int rn = n0 + row; if (rn >= N) rn = N - 1;
            size_t gb = (size_t)rn * Kv + kc4 + lseg;
            CP16(d + 2*MOFF, Bt + gb);
        }
        CP_COMMIT();
    };

    load_chunk(0);

    for (int c = 0; c < nch; c++) {
        if (c + 1 < nch) { load_chunk(c + 1); CP_WAIT1(); }
        else             { CP_WAIT0(); }
        __syncthreads();

        const uint32_t base = sb + (c & 1) * BUFSZ;
        const uint32_t ab = base + (wm * 64 + (lane & 15)) * SMS + ((lane >> 4) << 4);
        const uint32_t bb = base + 2*MOFF + (wn * 32 + (lane & 15)) * SMS + ((lane >> 4) << 4);

#pragma unroll
        for (int ks = 0; ks < 2; ks++) {
            const uint32_t ko = ks << 5;
            uint32_t ahf[16], alf[16], bf[8];
#pragma unroll
            for (int mt = 0; mt < 4; mt++) {
                LDSM4(&ahf[mt*4], ab + mt * (16*SMS) + ko);
                if (TWO_TERM) LDSM4(&alf[mt*4], ab + MOFF + mt * (16*SMS) + ko);
            }
#pragma unroll
            for (int q = 0; q < 2; q++)
                LDSM4(&bf[q*4], bb + q * (16*SMS) + ko);
#pragma unroll
            for (int mt = 0; mt < 4; mt++)
#pragma unroll
                for (int nt = 0; nt < 4; nt++) {
                    const int q = (nt >> 1) * 4, r = nt & 1;
                    MMAH(acc[mt][nt], &ahf[mt*4], bf[q+r], bf[q+2+r]);
                    if (TWO_TERM)
                        MMAH(acc[mt][nt], &alf[mt*4], bf[q+r], bf[q+2+r]);
                }
        }
        __syncthreads();
    }

    // epilogue (fused bias / residual / relu, fp32 and/or split-fp16 outputs)
#pragma unroll
    for (int mt = 0; mt < 4; mt++) {
        const int row0 = m0 + wm * 64 + mt * 16 + (lane >> 2);
#pragma unroll
        for (int nt = 0; nt < 4; nt++) {
            const int col = n0 + wn * 32 + nt * 8 + ((lane & 3) << 1);
            if (col >= N) continue;
            const float* d = acc[mt][nt];
#pragma unroll
            for (int h = 0; h < 2; h++) {
                const int r = row0 + h * 8;
                size_t o = (size_t)r * N + col;
#pragma unroll
                for (int j = 0; j < 2; j++) {
                    if (col + j >= N) break;
                    float x = d[h*2+j];
                    if (mode & 1) x += bias[col+j];
                    if (mode & 4) x += Res[o+j];
                    if (mode & 2) x = fmaxf(x, 0.f);
                    if (C)  C[o+j] = x;
                    if (Ch) split_store(x, Ch, Cl, o+j);
                }
            }
        }
    }
}

// ---------------------------------------------------------------------------
// Embedding + positional encoding, with fused fp16 split
// ---------------------------------------------------------------------------
__global__ __launch_bounds__(256) void embed_k(const int* __restrict__ ids,
                                               const float* __restrict__ emb,
                                               float* __restrict__ x,
                                               __half* __restrict__ xh,
                                               __half* __restrict__ xl)
{
    int t = blockIdx.x;
    int s = t % SS;
    int id = ids[t];
    const float* er = emb + (size_t)id * DD;
    size_t base = (size_t)t * DD;
    for (int d = threadIdx.x; d < DD; d += 256) {
        float ang = (float)s * powf(10000.0f, -2.0f * (float)d / (float)DD);
        float pe  = (d & 1) ? cosf(ang) : sinf(ang);
        float v = er[d] + pe;
        x[base + d] = v;
        split_store(v, xh, xl, base + d);
    }
}

// ---------------------------------------------------------------------------
// Weight transpose + fp16 convert: W[K,N] -> T[N,K]
// ---------------------------------------------------------------------------
__global__ __launch_bounds__(256) void wconvT_k(const float* __restrict__ W,
                                                __half* __restrict__ T,
                                                int K, int N)
{
    __shared__ float t[32][33];
    int k0 = blockIdx.y * 32, n0 = blockIdx.x * 32;
    int tx = threadIdx.x & 31, ty = threadIdx.x >> 5;
#pragma unroll
    for (int i = 0; i < 4; i++) {
        int k = k0 + ty + i * 8, n = n0 + tx;
        t[ty + i * 8][tx] = (k < K && n < N) ? W[(size_t)k * N + n] : 0.f;
    }
    __syncthreads();
#pragma unroll
    for (int i = 0; i < 4; i++) {
        int n = n0 + ty + i * 8, k = k0 + tx;
        if (n < N && k < K)
            T[(size_t)n * K + k] = __float2half_rn(t[tx][ty + i * 8]);
    }
}

// ---------------------------------------------------------------------------
// W_o head-block sum + transpose + fp16: T[c,r] = fp16(sum_h Wo[h*D+r, c])
// ---------------------------------------------------------------------------
__global__ __launch_bounds__(256) void wosumT_k(const float* __restrict__ Wo,
                                                __half* __restrict__ T)
{
    __shared__ float t[32][33];
    int r0 = blockIdx.y * 32, c0 = blockIdx.x * 32;
    int tx = threadIdx.x & 31, ty = threadIdx.x >> 5;
#pragma unroll
    for (int i = 0; i < 4; i++) {
        int r = r0 + ty + i * 8;
        float s = 0.f;
#pragma unroll
        for (int h = 0; h < HH; h++)
            s += Wo[((size_t)(h * DD + r)) * DD + c0 + tx];
        t[ty + i * 8][tx] = s;
    }
    __syncthreads();
#pragma unroll
    for (int i = 0; i < 4; i++) {
        int cc = c0 + ty + i * 8;
        int rr = r0 + tx;
        T[(size_t)cc * DD + rr] = __float2half_rn(t[tx][ty + i * 8]);
    }
}

// ---------------------------------------------------------------------------
// Causal flash attention (fp32, online softmax), fused fp16-split epilogue
// ---------------------------------------------------------------------------
#define QB 64
#define KB 32
__global__ __launch_bounds__(64) void attn_k(const float* __restrict__ qkv,
                                             __half* __restrict__ oh,
                                             __half* __restrict__ ol)
{
    const int qb = blockIdx.x;
    const int h  = blockIdx.y;
    const int b  = blockIdx.z;
    const int qi = qb * QB + threadIdx.x;
    const int tok = b * SS + qi;
    const int TD = 3 * DD;

    float qreg[HDIM];
#pragma unroll
    for (int d = 0; d < HDIM; d++)
        qreg[d] = qkv[(size_t)tok * TD + h * HDIM + d];

    float o[HDIM];
#pragma unroll
    for (int d = 0; d < HDIM; d++) o[d] = 0.f;
    float m = -1e30f, l = 0.f;

    __shared__ float sK[KB][HDIM];
    __shared__ float sV[KB][HDIM];

    const int kend = qb * QB + QB;
    for (int k0 = 0; k0 < kend; k0 += KB) {
        // vectorized cooperative load: KB*HDIM/4 = 512 float4 pairs
        for (int idx = threadIdx.x; idx < KB * (HDIM/4); idx += 64) {
            int r = idx >> 4;           // / 16
            int d4 = (idx & 15) << 2;
            size_t base = (size_t)(b * SS + k0 + r) * TD + h * HDIM + d4;
            *(float4*)&sK[r][d4] = *(const float4*)(qkv + base + DD);
            *(float4*)&sV[r][d4] = *(const float4*)(qkv + base + 2*DD);
        }
        __syncthreads();

        float sc[KB];
        float mt = -1e30f;
#pragma unroll
        for (int j = 0; j < KB; j++) {
            float s = 0.f;
#pragma unroll
            for (int d = 0; d < HDIM; d++) s = fmaf(qreg[d], sK[j][d], s);
            s *= 0.125f;
            if (k0 + j > qi) s = -1e30f;
            sc[j] = s;
            mt = fmaxf(mt, s);
        }
        float mnew = fmaxf(m, mt);
        float corr = __expf(m - mnew);
        l *= corr;
#pragma unroll
        for (int d = 0; d < HDIM; d++) o[d] *= corr;
#pragma unroll
        for (int j = 0; j < KB; j++) {
            float p = __expf(sc[j] - mnew);
            l += p;
#pragma unroll
            for (int d = 0; d < HDIM; d++) o[d] = fmaf(p, sV[j][d], o[d]);
        }
        m = mnew;
        __syncthreads();
    }

    float inv = 1.f / l;
#pragma unroll
    for (int d = 0; d < HDIM; d++) {
        size_t idx = (size_t)tok * DD + h * HDIM + d;
        split_store(o[d] * inv, oh, ol, idx);
    }
}

// ---------------------------------------------------------------------------
// LayerNorm over D=768, optional fp32 out + optional fused fp16 split out
// ---------------------------------------------------------------------------
__global__ __launch_bounds__(256) void layernorm_k(const float* __restrict__ X,
                                                   const float* __restrict__ g,
                                                   const float* __restrict__ b,
                                                   float* __restrict__ Y,
                                                   __half* __restrict__ Yh,
                                                   __half* __restrict__ Yl)
{
    int t = blockIdx.x;
    const float* xr = X + (size_t)t * DD;
    float vals[3];
    float s = 0.f, s2 = 0.f;
#pragma unroll
    for (int i = 0; i < 3; i++) {
        float v = xr[threadIdx.x + i * 256];
        vals[i] = v;
        s += v; s2 += v * v;
    }
#pragma unroll
    for (int o = 16; o > 0; o >>= 1) {
        s  += __shfl_xor_sync(0xFFFFFFFFu, s,  o);
        s2 += __shfl_xor_sync(0xFFFFFFFFu, s2, o);
    }
    __shared__ float rs[8], rs2[8];
    int w = threadIdx.x >> 5;
    if ((threadIdx.x & 31) == 0) { rs[w] = s; rs2[w] = s2; }
    __syncthreads();
    if (threadIdx.x < 32) {
        s  = (threadIdx.x < 8) ? rs [threadIdx.x] : 0.f;
        s2 = (threadIdx.x < 8) ? rs2[threadIdx.x] : 0.f;
#pragma unroll
        for (int o = 4; o > 0; o >>= 1) {
            s  += __shfl_xor_sync(0xFFFFFFFFu, s,  o);
            s2 += __shfl_xor_sync(0xFFFFFFFFu, s2, o);
        }
        if (threadIdx.x == 0) { rs[0] = s; rs2[0] = s2; }
    }
    __syncthreads();
    float mean = rs[0] * (1.f / DD);
    float var  = rs2[0] * (1.f / DD) - mean * mean;
    float rstd = rsqrtf(var + 1e-5f);
#pragma unroll
    for (int i = 0; i < 3; i++) {
        int d = threadIdx.x + i * 256;
        float v = (vals[i] - mean) * rstd * g[d] + b[d];
        size_t o = (size_t)t * DD + d;
        if (Y)  Y[o] = v;
        if (Yh) split_store(v, Yh, Yl, o);
    }
}

// ---------------------------------------------------------------------------
// Launch
// ---------------------------------------------------------------------------
static inline void run_gemm2(const __half* Ah, const __half* Al, const __half* Bt,
                             const float* bias, const float* Res,
                             float* C, __half* Ch, __half* Cl,
                             int M, int N, int K, int mode)
{
    dim3 grid(M / 128, (N + 127) / 128);
    tgemm_k<1><<<grid, 256, TGSM>>>((const uint4*)Ah, (const uint4*)Al,
                                    (const uint4*)Bt, bias, Res, C, Ch, Cl,
                                    M, N, K, mode);
}

static inline void run_gemm1(const __half* Ah, const __half* Bt,
                             const float* bias, float* C,
                             int M, int N, int K, int mode)
{
    dim3 grid(M / 128, (N + 127) / 128);
    tgemm_k<0><<<grid, 256, TGSM>>>((const uint4*)Ah, nullptr,
                                    (const uint4*)Bt, bias, nullptr,
                                    C, nullptr, nullptr, M, N, K, mode);
}

extern "C" void kernel_launch(void* const* d_in, const int* in_sizes, int n_in,
                              void* d_out, int out_size)
{
    const int*   ids    = (const int*)  d_in[0];
    const float* emb    = (const float*)d_in[1];
    const float* W_qkv  = (const float*)d_in[2];
    const float* b_qkv  = (const float*)d_in[3];
    const float* W_o    = (const float*)d_in[4];
    const float* b_o    = (const float*)d_in[5];
    const float* ln1_g  = (const float*)d_in[6];
    const float* ln1_b  = (const float*)d_in[7];
    const float* W_ff1  = (const float*)d_in[8];
    const float* b_ff1  = (const float*)d_in[9];
    const float* W_ff2  = (const float*)d_in[10];
    const float* b_ff2  = (const float*)d_in[11];
    const float* ln2_g  = (const float*)d_in[12];
    const float* ln2_b  = (const float*)d_in[13];
    const float* W_out  = (const float*)d_in[14];
    const float* b_out  = (const float*)d_in[15];
    float* out = (float*)d_out;

    cudaFuncSetAttribute(tgemm_k<1>, cudaFuncAttributeMaxDynamicSharedMemorySize, TGSM);
    cudaFuncSetAttribute(tgemm_k<0>, cudaFuncAttributeMaxDynamicSharedMemorySize, TGSM);

    float *px, *pqkv, *pmha, *ph1, *pffo;
    cudaGetSymbolAddress((void**)&px,   g_x);
    cudaGetSymbolAddress((void**)&pqkv, g_qkv);
    cudaGetSymbolAddress((void**)&pmha, g_mha);
    cudaGetSymbolAddress((void**)&ph1,  g_h1);
    cudaGetSymbolAddress((void**)&pffo, g_ffo);

    __half *xh,*xl,*ath,*atl,*h1h,*h1l,*ffh,*ffl,*h2h,*h2l;
    cudaGetSymbolAddress((void**)&xh,  g_xh);  cudaGetSymbolAddress((void**)&xl,  g_xl);
    cudaGetSymbolAddress((void**)&ath, g_ath); cudaGetSymbolAddress((void**)&atl, g_atl);
    cudaGetSymbolAddress((void**)&h1h, g_h1h); cudaGetSymbolAddress((void**)&h1l, g_h1l);
    cudaGetSymbolAddress((void**)&ffh, g_ffh); cudaGetSymbolAddress((void**)&ffl, g_ffl);
    cudaGetSymbolAddress((void**)&h2h, g_h2h); cudaGetSymbolAddress((void**)&h2l, g_h2l);

    __half *wq,*ws,*w1,*w2,*wo;
    cudaGetSymbolAddress((void**)&wq, g_wqkvT);
    cudaGetSymbolAddress((void**)&ws, g_wsumT);
    cudaGetSymbolAddress((void**)&w1, g_wff1T);
    cudaGetSymbolAddress((void**)&w2, g_wff2T);
    cudaGetSymbolAddress((void**)&wo, g_woutT);

    // Weight prep
    wconvT_k<<<dim3((3*DD + 31)/32, (DD + 31)/32), 256>>>(W_qkv, wq, DD, 3*DD);
    wosumT_k<<<dim3(DD/32, DD/32), 256>>>(W_o, ws);
    wconvT_k<<<dim3((FFD + 31)/32, (DD + 31)/32), 256>>>(W_ff1, w1, DD, FFD);
    wconvT_k<<<dim3((DD + 31)/32, (FFD + 31)/32), 256>>>(W_ff2, w2, FFD, DD);
    wconvT_k<<<dim3((VV + 31)/32, (DD + 31)/32), 256>>>(W_out, wo, DD, VV);

    // 1. embeddings + PE (fused split)
    embed_k<<<NTOK, 256>>>(ids, emb, px, xh, xl);

    // 2. QKV projection (fp32 out for attention)
    run_gemm2(xh, xl, wq, b_qkv, nullptr, pqkv, nullptr, nullptr,
              NTOK, 3*DD, DD, 1);

    // 3. attention (fused split epilogue)
    attn_k<<<dim3(SS/QB, HH, BB), 64>>>(pqkv, ath, atl);

    // 4. mha = attn @ Wsum + b_o + x
    run_gemm2(ath, atl, ws, b_o, px, pmha, nullptr, nullptr,
              NTOK, DD, DD, 1|4);

    // 5. LN1 (fp32 residual + split)
    layernorm_k<<<NTOK, 256>>>(pmha, ln1_g, ln1_b, ph1, h1h, h1l);

    // 6. FF1 + relu (split-only out)
    run_gemm2(h1h, h1l, w1, b_ff1, nullptr, nullptr, ffh, ffl,
              NTOK, FFD, DD, 1|2);

    // 7. FF2 + residual (fp32 out)
    run_gemm2(ffh, ffl, w2, b_ff2, ph1, pffo, nullptr, nullptr,
              NTOK, DD, FFD, 1|4);

    // 8. LN2 (split-only out; lo half unused by vocab but cheap)
    layernorm_k<<<NTOK, 256>>>(pffo, ln2_g, ln2_b, nullptr, h2h, h2l);

    // 9. vocab projection -- single-term fp16 (the 632->316 GF cut)
    run_gemm1(h2h, wo, b_out, out, NTOK, VV, DD, 1);
}

// round 6
// speedup vs baseline: 5.3901x; 1.4912x over previous
#include <cuda_runtime.h>
#include <cuda_fp16.h>
#include <math.h>
#include <stdint.h>

// Problem constants
#define BB   2
#define SS   2048
#define DD   768
#define HH   12
#define VV   50257
#define FFD  3072
#define HDIM 64
#define NTOK (BB*SS)

// ---------------------------------------------------------------------------
// Scratch (static device globals -- no allocation allowed)
// ---------------------------------------------------------------------------
__device__ float g_x   [NTOK*DD];      // embeddings + PE (residual for step 4)
__device__ float g_mha [NTOK*DD];
__device__ float g_h1  [NTOK*DD];      // LN1 out fp32 (residual for step 7)
__device__ float g_ffo [NTOK*DD];

// fp16 hi/lo splits of activations (A operands)
__device__ __half g_xh [NTOK*DD],  g_xl [NTOK*DD];
__device__ __half g_ath[NTOK*DD],  g_atl[NTOK*DD];
__device__ __half g_h1h[NTOK*DD],  g_h1l[NTOK*DD];
__device__ __half g_ffh[NTOK*FFD], g_ffl[NTOK*FFD];
__device__ __half g_h2h[NTOK*DD],  g_h2l[NTOK*DD];

// head-major attention operands [b][h][s][64]
__device__ __half g_qh[NTOK*DD], g_ql[NTOK*DD];
__device__ __half g_kh[NTOK*DD];
__device__ __half g_vh[NTOK*DD];

// fp16 transposed weights [N,K]
__device__ __half g_wqkvT[3*DD*DD];
__device__ __half g_wsumT[DD*DD];
__device__ __half g_wff1T[(size_t)FFD*DD];
__device__ __half g_wff2T[(size_t)DD*FFD];
__device__ __half g_woutT[(size_t)VV*DD];

// ---------------------------------------------------------------------------
// PTX helpers (plain sm_103-safe: cp.async, ldmatrix, mma.sync only)
// ---------------------------------------------------------------------------
__device__ __forceinline__ uint32_t smem_u32(const void* p) {
    uint32_t a;
    asm("{ .reg .u64 t; cvta.to.shared.u64 t, %1; cvt.u32.u64 %0, t; }"
        : "=r"(a) : "l"(p));
    return a;
}

#define CP16(dst, src) \
    asm volatile("cp.async.cg.shared.global [%0], [%1], 16;" \
                 :: "r"(dst), "l"(src) : "memory")
#define CP_COMMIT() asm volatile("cp.async.commit_group;" ::: "memory")
#define CP_WAIT1()  asm volatile("cp.async.wait_group 1;"  ::: "memory")
#define CP_WAIT0()  asm volatile("cp.async.wait_group 0;"  ::: "memory")

#define LDSM4(r, a) \
    asm volatile("ldmatrix.sync.aligned.m8n8.x4.shared.b16 {%0,%1,%2,%3}, [%4];" \
        : "=r"((r)[0]), "=r"((r)[1]), "=r"((r)[2]), "=r"((r)[3]) : "r"(a))

#define LDSM4T(r, a) \
    asm volatile("ldmatrix.sync.aligned.m8n8.x4.trans.shared.b16 {%0,%1,%2,%3}, [%4];" \
        : "=r"((r)[0]), "=r"((r)[1]), "=r"((r)[2]), "=r"((r)[3]) : "r"(a))

#define MMAH(d, a, b0, b1) \
    asm volatile("mma.sync.aligned.m16n8k16.row.col.f32.f16.f16.f32 " \
        "{%0,%1,%2,%3}, {%4,%5,%6,%7}, {%8,%9}, {%0,%1,%2,%3};" \
        : "+f"((d)[0]), "+f"((d)[1]), "+f"((d)[2]), "+f"((d)[3]) \
        : "r"((a)[0]), "r"((a)[1]), "r"((a)[2]), "r"((a)[3]), \
          "r"(b0), "r"(b1))

__device__ __forceinline__ void split_store(float x, __half* H, __half* L, size_t o) {
    __half h = __float2half_rn(x);
    H[o] = h;
    L[o] = __float2half_rn(x - __half2float(h));
}

__device__ __forceinline__ uint32_t f22u(float a, float b) {
    __half2 t = __floats2half2_rn(a, b);
    return *reinterpret_cast<uint32_t*>(&t);
}

// ---------------------------------------------------------------------------
// fp16 mma.sync GEMM: C[M,N] = A[M,K] @ Bt[N,K]^T
//   TWO_TERM=1: A = Ah + Al (exact fp32 reconstruction), 2 MMAs / frag pair
//   TWO_TERM=0: A = Ah single fp16 (vocab projection)
// mode: 1=+bias, 2=relu, 4=+Res, 8=QKV head-major scatter
// ---------------------------------------------------------------------------
#define SMS   80
#define MOFF  10240
#define BUFSZ 30720
#define TGSM  (2*BUFSZ)

template<int TWO_TERM>
__global__ __launch_bounds__(256, 1) void tgemm_k(
    const uint4* __restrict__ Ah, const uint4* __restrict__ Al,
    const uint4* __restrict__ Bt,
    const float* __restrict__ bias, const float* __restrict__ Res,
    float* __restrict__ C, __half* __restrict__ Ch, __half* __restrict__ Cl,
    __half* __restrict__ K16, __half* __restrict__ V16,
    int M, int N, int K, int mode)
{
    extern __shared__ char sm[];
    const uint32_t sb = smem_u32(sm);
    const int tid  = threadIdx.x;
    const int lane = tid & 31;
    const int warp = tid >> 5;
    const int wm = warp >> 2;
    const int wn = warp & 3;
    const int m0 = blockIdx.x * 128;
    const int n0 = blockIdx.y * 128;

    const int Kv  = K >> 3;
    const int nch = K >> 5;
    const int lrow = tid >> 2;
    const int lseg = tid & 3;

    float acc[4][4][4];
#pragma unroll
    for (int i = 0; i < 4; i++)
#pragma unroll
        for (int j = 0; j < 4; j++)
#pragma unroll
            for (int k = 0; k < 4; k++) acc[i][j][k] = 0.f;

    auto load_chunk = [&](int c) {
        const int b = c & 1;
        const uint32_t base = sb + b * BUFSZ;
        const int kc4 = c << 2;
#pragma unroll
        for (int it = 0; it < 2; it++) {
            int row = lrow + it * 64;
            uint32_t d = base + row * SMS + lseg * 16;
            size_t ga = (size_t)(m0 + row) * Kv + kc4 + lseg;
            CP16(d,          Ah + ga);
            if (TWO_TERM) CP16(d + MOFF, Al + ga);
            int rn = n0 + row; if (rn >= N) rn = N - 1;
            size_t gb = (size_t)rn * Kv + kc4 + lseg;
            CP16(d + 2*MOFF, Bt + gb);
        }
        CP_COMMIT();
    };

    load_chunk(0);

    for (int c = 0; c < nch; c++) {
        if (c + 1 < nch) { load_chunk(c + 1); CP_WAIT1(); }
        else             { CP_WAIT0(); }
        __syncthreads();

        const uint32_t base = sb + (c & 1) * BUFSZ;
        const uint32_t ab = base + (wm * 64 + (lane & 15)) * SMS + ((lane >> 4) << 4);
        const uint32_t bb = base + 2*MOFF + (wn * 32 + (lane & 15)) * SMS + ((lane >> 4) << 4);

#pragma unroll
        for (int ks = 0; ks < 2; ks++) {
            const uint32_t ko = ks << 5;
            uint32_t ahf[16], alf[16], bf[8];
#pragma unroll
            for (int mt = 0; mt < 4; mt++) {
                LDSM4(&ahf[mt*4], ab + mt * (16*SMS) + ko);
                if (TWO_TERM) LDSM4(&alf[mt*4], ab + MOFF + mt * (16*SMS) + ko);
            }
#pragma unroll
            for (int q = 0; q < 2; q++)
                LDSM4(&bf[q*4], bb + q * (16*SMS) + ko);
#pragma unroll
            for (int mt = 0; mt < 4; mt++)
#pragma unroll
                for (int nt = 0; nt < 4; nt++) {
                    const int q = (nt >> 1) * 4, r = nt & 1;
                    MMAH(acc[mt][nt], &ahf[mt*4], bf[q+r], bf[q+2+r]);
                    if (TWO_TERM)
                        MMAH(acc[mt][nt], &alf[mt*4], bf[q+r], bf[q+2+r]);
                }
        }
        __syncthreads();
    }

    // epilogue
#pragma unroll
    for (int mt = 0; mt < 4; mt++) {
        const int row0 = m0 + wm * 64 + mt * 16 + (lane >> 2);
#pragma unroll
        for (int nt = 0; nt < 4; nt++) {
            const int col = n0 + wn * 32 + nt * 8 + ((lane & 3) << 1);
            if (col >= N) continue;
            const float* d = acc[mt][nt];
#pragma unroll
            for (int h = 0; h < 2; h++) {
                const int r = row0 + h * 8;
                size_t o = (size_t)r * N + col;
#pragma unroll
                for (int j = 0; j < 2; j++) {
                    if (col + j >= N) break;
                    float x = d[h*2+j];
                    if (mode & 1) x += bias[col+j];
                    if (mode & 4) x += Res[o+j];
                    if (mode & 2) x = fmaxf(x, 0.f);
                    if (mode & 8) {
                        // head-major scatter: [b][head][s][64]
                        int cc = col + j;
                        int bq = r >> 11, sq = r & 2047;
                        int part = cc / DD;          // 0=Q 1=K 2=V
                        int cd = cc - part * DD;
                        int hd = cd >> 6, dd = cd & 63;
                        size_t oo = (((size_t)(bq*HH + hd))*SS + sq)*64 + dd;
                        if (part == 0)      split_store(x, Ch, Cl, oo);
                        else if (part == 1) K16[oo] = __float2half_rn(x);
                        else                V16[oo] = __float2half_rn(x);
                    } else {
                        if (C)  C[o+j] = x;
                        if (Ch) split_store(x, Ch, Cl, o+j);
                    }
                }
            }
        }
    }
}

// ---------------------------------------------------------------------------
// Embedding + positional encoding, with fused fp16 split
// ---------------------------------------------------------------------------
__global__ __launch_bounds__(256) void embed_k(const int* __restrict__ ids,
                                               const float* __restrict__ emb,
                                               float* __restrict__ x,
                                               __half* __restrict__ xh,
                                               __half* __restrict__ xl)
{
    int t = blockIdx.x;
    int s = t % SS;
    int id = ids[t];
    const float* er = emb + (size_t)id * DD;
    size_t base = (size_t)t * DD;
    for (int d = threadIdx.x; d < DD; d += 256) {
        float ang = (float)s * powf(10000.0f, -2.0f * (float)d / (float)DD);
        float pe  = (d & 1) ? cosf(ang) : sinf(ang);
        float v = er[d] + pe;
        x[base + d] = v;
        split_store(v, xh, xl, base + d);
    }
}

// ---------------------------------------------------------------------------
// Weight transpose + fp16 convert: W[K,N] -> T[N,K]
// ---------------------------------------------------------------------------
__global__ __launch_bounds__(256) void wconvT_k(const float* __restrict__ W,
                                                __half* __restrict__ T,
                                                int K, int N)
{
    __shared__ float t[32][33];
    int k0 = blockIdx.y * 32, n0 = blockIdx.x * 32;
    int tx = threadIdx.x & 31, ty = threadIdx.x >> 5;
#pragma unroll
    for (int i = 0; i < 4; i++) {
        int k = k0 + ty + i * 8, n = n0 + tx;
        t[ty + i * 8][tx] = (k < K && n < N) ? W[(size_t)k * N + n] : 0.f;
    }
    __syncthreads();
#pragma unroll
    for (int i = 0; i < 4; i++) {
        int n = n0 + ty + i * 8, k = k0 + tx;
        if (n < N && k < K)
            T[(size_t)n * K + k] = __float2half_rn(t[tx][ty + i * 8]);
    }
}

// ---------------------------------------------------------------------------
// W_o head-block sum + transpose + fp16
// ---------------------------------------------------------------------------
__global__ __launch_bounds__(256) void wosumT_k(const float* __restrict__ Wo,
                                                __half* __restrict__ T)
{
    __shared__ float t[32][33];
    int r0 = blockIdx.y * 32, c0 = blockIdx.x * 32;
    int tx = threadIdx.x & 31, ty = threadIdx.x >> 5;
#pragma unroll
    for (int i = 0; i < 4; i++) {
        int r = r0 + ty + i * 8;
        float s = 0.f;
#pragma unroll
        for (int h = 0; h < HH; h++)
            s += Wo[((size_t)(h * DD + r)) * DD + c0 + tx];
        t[ty + i * 8][tx] = s;
    }
    __syncthreads();
#pragma unroll
    for (int i = 0; i < 4; i++) {
        int cc = c0 + ty + i * 8;
        int rr = r0 + tx;
        T[(size_t)cc * DD + rr] = __float2half_rn(t[tx][ty + i * 8]);
    }
}

// ---------------------------------------------------------------------------
// Tensor-core causal flash attention (FA2 style).
// grid (S/64, H, B), 128 threads (4 warps x 16 Q rows).
// Q: 2-term fp16 split (exact). K, V, P: single fp16.
// smem: Qh,Ql,K[2],V[2] tiles 64x64 halfs @ 144B row stride.
// ---------------------------------------------------------------------------
#define SMSA 144
#define ATILE 9216          // 64*144
#define ASM_TOTAL (6*ATILE) // 55296

__global__ __launch_bounds__(128, 1) void attn_k(
    const __half* __restrict__ Qh, const __half* __restrict__ Ql,
    const __half* __restrict__ Kh, const __half* __restrict__ Vh,
    __half* __restrict__ oh, __half* __restrict__ ol)
{
    extern __shared__ char sm[];
    const uint32_t sb = smem_u32(sm);
    const int qb = blockIdx.x, hh = blockIdx.y, bb = blockIdx.z;
    const int tid = threadIdx.x, lane = tid & 31, warp = tid >> 5;
    const size_t hbase = ((size_t)(bb*HH + hh)) * SS * 64;

    const uint32_t sQh = sb;
    const uint32_t sQl = sb + ATILE;
    const uint32_t sK0 = sb + 2*ATILE;
    const uint32_t sV0 = sb + 4*ATILE;

    // Q tiles (hi + lo)
    for (int idx = tid; idx < 512; idx += 128) {
        int r = idx >> 3, seg = idx & 7;
        size_t g = hbase + (size_t)(qb*64 + r)*64 + seg*8;
        CP16(sQh + r*SMSA + seg*16, (const uint4*)(Qh + g));
        CP16(sQl + r*SMSA + seg*16, (const uint4*)(Ql + g));
    }
    CP_COMMIT();

    auto loadKV = [&](int j) {
        uint32_t kb = sK0 + (j & 1)*ATILE;
        uint32_t vb = sV0 + (j & 1)*ATILE;
        for (int idx = tid; idx < 512; idx += 128) {
            int r = idx >> 3, seg = idx & 7;
            size_t g = hbase + (size_t)(j*64 + r)*64 + seg*8;
            CP16(kb + r*SMSA + seg*16, (const uint4*)(Kh + g));
            CP16(vb + r*SMSA + seg*16, (const uint4*)(Vh + g));
        }
        CP_COMMIT();
    };

    loadKV(0);

    uint32_t qfh[4][4], qfl[4][4];      // Q A-frags per k-step
    float oacc[8][4];
    float m[2] = {-1e30f, -1e30f}, l[2] = {0.f, 0.f};
#pragma unroll
    for (int nt = 0; nt < 8; nt++)
#pragma unroll
        for (int j2 = 0; j2 < 4; j2++) oacc[nt][j2] = 0.f;

    const int rowg = lane >> 2;         // 0..7
    const int colg = (lane & 3) << 1;   // 0,2,4,6
    const uint32_t aoff = (warp*16 + (lane & 15))*SMSA + ((lane >> 4) << 4);

    for (int j = 0; j <= qb; j++) {
        if (j < qb) loadKV(j + 1);
        if (j < qb) CP_WAIT1(); else CP_WAIT0();
        __syncthreads();

        if (j == 0) {
#pragma unroll
            for (int kk = 0; kk < 4; kk++) {
                LDSM4(qfh[kk], sQh + aoff + kk*32);
                LDSM4(qfl[kk], sQl + aoff + kk*32);
            }
        }

        const uint32_t kb = sK0 + (j & 1)*ATILE;
        const uint32_t vb = sV0 + (j & 1)*ATILE;

        // ---- S = Q K^T (2-term) ----
        float sacc[8][4];
#pragma unroll
        for (int nt = 0; nt < 8; nt++)
#pragma unroll
            for (int j2 = 0; j2 < 4; j2++) sacc[nt][j2] = 0.f;

#pragma unroll
        for (int kk = 0; kk < 4; kk++) {
            uint32_t bf[16];
#pragma unroll
            for (int q = 0; q < 4; q++)
                LDSM4(&bf[q*4], kb + (q*16 + (lane & 15))*SMSA
                                  + ((lane >> 4) << 4) + kk*32);
#pragma unroll
            for (int nt = 0; nt < 8; nt++) {
                const int q = (nt >> 1)*4, r = nt & 1;
                MMAH(sacc[nt], qfh[kk], bf[q+r], bf[q+2+r]);
                MMAH(sacc[nt], qfl[kk], bf[q+r], bf[q+2+r]);
            }
        }

        // ---- scale + causal mask ----
        const int grow0 = qb*64 + warp*16 + rowg;
#pragma unroll
        for (int nt = 0; nt < 8; nt++)
#pragma unroll
            for (int j2 = 0; j2 < 4; j2++) {
                float s = sacc[nt][j2] * 0.125f;
                if (j == qb) {
                    int gc = j*64 + nt*8 + colg + (j2 & 1);
                    int gr = grow0 + ((j2 >> 1) << 3);
                    if (gc > gr) s = -1e30f;
                }
                sacc[nt][j2] = s;
            }

        // ---- online softmax ----
        float mt[2] = {-1e30f, -1e30f};
#pragma unroll
        for (int nt = 0; nt < 8; nt++) {
            mt[0] = fmaxf(mt[0], fmaxf(sacc[nt][0], sacc[nt][1]));
            mt[1] = fmaxf(mt[1], fmaxf(sacc[nt][2], sacc[nt][3]));
        }
#pragma unroll
        for (int i = 0; i < 2; i++) {
            mt[i] = fmaxf(mt[i], __shfl_xor_sync(0xFFFFFFFFu, mt[i], 1));
            mt[i] = fmaxf(mt[i], __shfl_xor_sync(0xFFFFFFFFu, mt[i], 2));
        }
        float corr[2], mnew[2];
#pragma unroll
        for (int i = 0; i < 2; i++) {
            mnew[i] = fmaxf(m[i], mt[i]);
            corr[i] = __expf(m[i] - mnew[i]);
            m[i] = mnew[i];
        }
        float ls[2] = {0.f, 0.f};
#pragma unroll
        for (int nt = 0; nt < 8; nt++) {
            sacc[nt][0] = __expf(sacc[nt][0] - mnew[0]);
            sacc[nt][1] = __expf(sacc[nt][1] - mnew[0]);
            sacc[nt][2] = __expf(sacc[nt][2] - mnew[1]);
            sacc[nt][3] = __expf(sacc[nt][3] - mnew[1]);
            ls[0] += sacc[nt][0] + sacc[nt][1];
            ls[1] += sacc[nt][2] + sacc[nt][3];
        }
#pragma unroll
        for (int i = 0; i < 2; i++) {
            ls[i] += __shfl_xor_sync(0xFFFFFFFFu, ls[i], 1);
            ls[i] += __shfl_xor_sync(0xFFFFFFFFu, ls[i], 2);
            l[i] = l[i]*corr[i] + ls[i];
        }
#pragma unroll
        for (int nt = 0; nt < 8; nt++) {
            oacc[nt][0] *= corr[0]; oacc[nt][1] *= corr[0];
            oacc[nt][2] *= corr[1]; oacc[nt][3] *= corr[1];
        }

        // ---- O += P V ----
#pragma unroll
        for (int kt = 0; kt < 4; kt++) {
            uint32_t pa[4];
            pa[0] = f22u(sacc[2*kt  ][0], sacc[2*kt  ][1]);
            pa[1] = f22u(sacc[2*kt  ][2], sacc[2*kt  ][3]);
            pa[2] = f22u(sacc[2*kt+1][0], sacc[2*kt+1][1]);
            pa[3] = f22u(sacc[2*kt+1][2], sacc[2*kt+1][3]);
            uint32_t vf[16];
#pragma unroll
            for (int q = 0; q < 4; q++)
                LDSM4T(&vf[q*4], vb + (kt*16 + (lane & 15))*SMSA
                                    + q*32 + ((lane >> 4) << 4));
#pragma unroll
            for (int nt = 0; nt < 8; nt++) {
                const int base = (nt >> 1)*4 + ((nt & 1) << 1);
                MMAH(oacc[nt], pa, vf[base], vf[base+1]);
            }
        }
        __syncthreads();
    }

    // ---- output: /l, split fp16 store into [tok][768] ----
    float inv[2] = {1.f / l[0], 1.f / l[1]};
#pragma unroll
    for (int nt = 0; nt < 8; nt++)
#pragma unroll
        for (int j2 = 0; j2 < 4; j2++) {
            int srow = qb*64 + warp*16 + rowg + ((j2 >> 1) << 3);
            int tok = bb*SS + srow;
            int col = hh*64 + nt*8 + colg + (j2 & 1);
            split_store(oacc[nt][j2] * inv[j2 >> 1], oh, ol,
                        (size_t)tok*DD + col);
        }
}

// ---------------------------------------------------------------------------
// LayerNorm over D=768, optional fp32 out + fused fp16 split out
// ---------------------------------------------------------------------------
__global__ __launch_bounds__(256) void layernorm_k(const float* __restrict__ X,
                                                   const float* __restrict__ g,
                                                   const float* __restrict__ b,
                                                   float* __restrict__ Y,
                                                   __half* __restrict__ Yh,
                                                   __half* __restrict__ Yl)
{
    int t = blockIdx.x;
    const float* xr = X + (size_t)t * DD;
    float vals[3];
    float s = 0.f, s2 = 0.f;
#pragma unroll
    for (int i = 0; i < 3; i++) {
        float v = xr[threadIdx.x + i * 256];
        vals[i] = v;
        s += v; s2 += v * v;
    }
#pragma unroll
    for (int o = 16; o > 0; o >>= 1) {
        s  += __shfl_xor_sync(0xFFFFFFFFu, s,  o);
        s2 += __shfl_xor_sync(0xFFFFFFFFu, s2, o);
    }
    __shared__ float rs[8], rs2[8];
    int w = threadIdx.x >> 5;
    if ((threadIdx.x & 31) == 0) { rs[w] = s; rs2[w] = s2; }
    __syncthreads();
    if (threadIdx.x < 32) {
        s  = (threadIdx.x < 8) ? rs [threadIdx.x] : 0.f;
        s2 = (threadIdx.x < 8) ? rs2[threadIdx.x] : 0.f;
#pragma unroll
        for (int o = 4; o > 0; o >>= 1) {
            s  += __shfl_xor_sync(0xFFFFFFFFu, s,  o);
            s2 += __shfl_xor_sync(0xFFFFFFFFu, s2, o);
        }
        if (threadIdx.x == 0) { rs[0] = s; rs2[0] = s2; }
    }
    __syncthreads();
    float mean = rs[0] * (1.f / DD);
    float var  = rs2[0] * (1.f / DD) - mean * mean;
    float rstd = rsqrtf(var + 1e-5f);
#pragma unroll
    for (int i = 0; i < 3; i++) {
        int d = threadIdx.x + i * 256;
        float v = (vals[i] - mean) * rstd * g[d] + b[d];
        size_t o = (size_t)t * DD + d;
        if (Y)  Y[o] = v;
        if (Yh) split_store(v, Yh, Yl, o);
    }
}

// ---------------------------------------------------------------------------
// Launch
// ---------------------------------------------------------------------------
static inline void run_gemm2(const __half* Ah, const __half* Al, const __half* Bt,
                             const float* bias, const float* Res,
                             float* C, __half* Ch, __half* Cl,
                             __half* K16, __half* V16,
                             int M, int N, int K, int mode)
{
    dim3 grid(M / 128, (N + 127) / 128);
    tgemm_k<1><<<grid, 256, TGSM>>>((const uint4*)Ah, (const uint4*)Al,
                                    (const uint4*)Bt, bias, Res, C, Ch, Cl,
                                    K16, V16, M, N, K, mode);
}

static inline void run_gemm1(const __half* Ah, const __half* Bt,
                             const float* bias, float* C,
                             int M, int N, int K, int mode)
{
    dim3 grid(M / 128, (N + 127) / 128);
    tgemm_k<0><<<grid, 256, TGSM>>>((const uint4*)Ah, nullptr,
                                    (const uint4*)Bt, bias, nullptr,
                                    C, nullptr, nullptr, nullptr, nullptr,
                                    M, N, K, mode);
}

extern "C" void kernel_launch(void* const* d_in, const int* in_sizes, int n_in,
                              void* d_out, int out_size)
{
    const int*   ids    = (const int*)  d_in[0];
    const float* emb    = (const float*)d_in[1];
    const float* W_qkv  = (const float*)d_in[2];
    const float* b_qkv  = (const float*)d_in[3];
    const float* W_o    = (const float*)d_in[4];
    const float* b_o    = (const float*)d_in[5];
    const float* ln1_g  = (const float*)d_in[6];
    const float* ln1_b  = (const float*)d_in[7];
    const float* W_ff1  = (const float*)d_in[8];
    const float* b_ff1  = (const float*)d_in[9];
    const float* W_ff2  = (const float*)d_in[10];
    const float* b_ff2  = (const float*)d_in[11];
    const float* ln2_g  = (const float*)d_in[12];
    const float* ln2_b  = (const float*)d_in[13];
    const float* W_out  = (const float*)d_in[14];
    const float* b_out  = (const float*)d_in[15];
    float* out = (float*)d_out;

    cudaFuncSetAttribute(tgemm_k<1>, cudaFuncAttributeMaxDynamicSharedMemorySize, TGSM);
    cudaFuncSetAttribute(tgemm_k<0>, cudaFuncAttributeMaxDynamicSharedMemorySize, TGSM);
    cudaFuncSetAttribute(attn_k, cudaFuncAttributeMaxDynamicSharedMemorySize, ASM_TOTAL);

    float *px, *pmha, *ph1, *pffo;
    cudaGetSymbolAddress((void**)&px,   g_x);
    cudaGetSymbolAddress((void**)&pmha, g_mha);
    cudaGetSymbolAddress((void**)&ph1,  g_h1);
    cudaGetSymbolAddress((void**)&pffo, g_ffo);

    __half *xh,*xl,*ath,*atl,*h1h,*h1l,*ffh,*ffl,*h2h,*h2l;
    cudaGetSymbolAddress((void**)&xh,  g_xh);  cudaGetSymbolAddress((void**)&xl,  g_xl);
    cudaGetSymbolAddress((void**)&ath, g_ath); cudaGetSymbolAddress((void**)&atl, g_atl);
    cudaGetSymbolAddress((void**)&h1h, g_h1h); cudaGetSymbolAddress((void**)&h1l, g_h1l);
    cudaGetSymbolAddress((void**)&ffh, g_ffh); cudaGetSymbolAddress((void**)&ffl, g_ffl);
    cudaGetSymbolAddress((void**)&h2h, g_h2h); cudaGetSymbolAddress((void**)&h2l, g_h2l);

    __half *qh,*ql,*kh,*vh;
    cudaGetSymbolAddress((void**)&qh, g_qh); cudaGetSymbolAddress((void**)&ql, g_ql);
    cudaGetSymbolAddress((void**)&kh, g_kh); cudaGetSymbolAddress((void**)&vh, g_vh);

    __half *wq,*ws,*w1,*w2,*wo;
    cudaGetSymbolAddress((void**)&wq, g_wqkvT);
    cudaGetSymbolAddress((void**)&ws, g_wsumT);
    cudaGetSymbolAddress((void**)&w1, g_wff1T);
    cudaGetSymbolAddress((void**)&w2, g_wff2T);
    cudaGetSymbolAddress((void**)&wo, g_woutT);

    // Weight prep
    wconvT_k<<<dim3((3*DD + 31)/32, (DD + 31)/32), 256>>>(W_qkv, wq, DD, 3*DD);
    wosumT_k<<<dim3(DD/32, DD/32), 256>>>(W_o, ws);
    wconvT_k<<<dim3((FFD + 31)/32, (DD + 31)/32), 256>>>(W_ff1, w1, DD, FFD);
    wconvT_k<<<dim3((DD + 31)/32, (FFD + 31)/32), 256>>>(W_ff2, w2, FFD, DD);
    wconvT_k<<<dim3((VV + 31)/32, (DD + 31)/32), 256>>>(W_out, wo, DD, VV);

    // 1. embeddings + PE (fused split)
    embed_k<<<NTOK, 256>>>(ids, emb, px, xh, xl);

    // 2. QKV projection -> head-major fp16 Q(hi/lo), K, V
    run_gemm2(xh, xl, wq, b_qkv, nullptr, nullptr, qh, ql, kh, vh,
              NTOK, 3*DD, DD, 1|8);

    // 3. tensor-core flash attention (fused split epilogue)
    attn_k<<<dim3(SS/64, HH, BB), 128, ASM_TOTAL>>>(qh, ql, kh, vh, ath, atl);

    // 4. mha = attn @ Wsum + b_o + x
    run_gemm2(ath, atl, ws, b_o, px, pmha, nullptr, nullptr, nullptr, nullptr,
              NTOK, DD, DD, 1|4);

    // 5. LN1 (fp32 residual + split)
    layernorm_k<<<NTOK, 256>>>(pmha, ln1_g, ln1_b, ph1, h1h, h1l);

    // 6. FF1 + relu (split-only out)
    run_gemm2(h1h, h1l, w1, b_ff1, nullptr, nullptr, ffh, ffl, nullptr, nullptr,
              NTOK, FFD, DD, 1|2);

    // 7. FF2 + residual (fp32 out)
    run_gemm2(ffh, ffl, w2, b_ff2, ph1, pffo, nullptr, nullptr, nullptr, nullptr,
              NTOK, DD, FFD, 1|4);

    // 8. LN2 (split out)
    layernorm_k<<<NTOK, 256>>>(pffo, ln2_g, ln2_b, nullptr, h2h, h2l);

    // 9. vocab projection -- single-term fp16
    run_gemm1(h2h, wo, b_out, out, NTOK, VV, DD, 1);
}

// round 8
// speedup vs baseline: 6.1414x; 1.1394x over previous
#include <cuda_runtime.h>
#include <cuda_fp16.h>
#include <math.h>
#include <stdint.h>

// Problem constants
#define BB   2
#define SS   2048
#define DD   768
#define HH   12
#define VV   50257
#define FFD  3072
#define HDIM 64
#define NTOK (BB*SS)

// ---------------------------------------------------------------------------
// Scratch (static device globals -- no allocation allowed)
// ---------------------------------------------------------------------------
__device__ float g_x   [NTOK*DD];      // embeddings + PE (residual for step 4)
__device__ float g_mha [NTOK*DD];
__device__ float g_h1  [NTOK*DD];      // LN1 out fp32 (residual for step 7)
__device__ float g_ffo [NTOK*DD];
__device__ float g_pebase[DD];         // 10000^(-2d/D)

// fp16 activations (A operands, single-term)
__device__ __half g_xh [NTOK*DD];
__device__ __half g_ath[NTOK*DD];
__device__ __half g_h1h[NTOK*DD];
__device__ __half g_ffh[NTOK*FFD];
__device__ __half g_h2h[NTOK*DD];

// head-major attention operands [b][h][s][64] (Q keeps hi/lo split)
__device__ __half g_qh[NTOK*DD], g_ql[NTOK*DD];
__device__ __half g_kh[NTOK*DD];
__device__ __half g_vh[NTOK*DD];

// fp16 transposed weights [N,K]
__device__ __half g_wqkvT[3*DD*DD];
__device__ __half g_wsumT[DD*DD];
__device__ __half g_wff1T[(size_t)FFD*DD];
__device__ __half g_wff2T[(size_t)DD*FFD];
__device__ __half g_woutT[(size_t)VV*DD];

// ---------------------------------------------------------------------------
// PTX helpers (plain sm_103-safe: cp.async, ldmatrix, mma.sync only)
// ---------------------------------------------------------------------------
__device__ __forceinline__ uint32_t smem_u32(const void* p) {
    uint32_t a;
    asm("{ .reg .u64 t; cvta.to.shared.u64 t, %1; cvt.u32.u64 %0, t; }"
        : "=r"(a) : "l"(p));
    return a;
}

#define CP16(dst, src) \
    asm volatile("cp.async.cg.shared.global [%0], [%1], 16;" \
                 :: "r"(dst), "l"(src) : "memory")
#define CP_COMMIT() asm volatile("cp.async.commit_group;" ::: "memory")
#define CP_WAIT1()  asm volatile("cp.async.wait_group 1;"  ::: "memory")
#define CP_WAIT0()  asm volatile("cp.async.wait_group 0;"  ::: "memory")

#define LDSM4(r, a) \
    asm volatile("ldmatrix.sync.aligned.m8n8.x4.shared.b16 {%0,%1,%2,%3}, [%4];" \
        : "=r"((r)[0]), "=r"((r)[1]), "=r"((r)[2]), "=r"((r)[3]) : "r"(a))

#define LDSM4T(r, a) \
    asm volatile("ldmatrix.sync.aligned.m8n8.x4.trans.shared.b16 {%0,%1,%2,%3}, [%4];" \
        : "=r"((r)[0]), "=r"((r)[1]), "=r"((r)[2]), "=r"((r)[3]) : "r"(a))

#define MMAH(d, a, b0, b1) \
    asm volatile("mma.sync.aligned.m16n8k16.row.col.f32.f16.f16.f32 " \
        "{%0,%1,%2,%3}, {%4,%5,%6,%7}, {%8,%9}, {%0,%1,%2,%3};" \
        : "+f"((d)[0]), "+f"((d)[1]), "+f"((d)[2]), "+f"((d)[3]) \
        : "r"((a)[0]), "r"((a)[1]), "r"((a)[2]), "r"((a)[3]), \
          "r"(b0), "r"(b1))

__device__ __forceinline__ void split_store(float x, __half* H, __half* L, size_t o) {
    __half h = __float2half_rn(x);
    H[o] = h;
    L[o] = __float2half_rn(x - __half2float(h));
}

__device__ __forceinline__ uint32_t f22u(float a, float b) {
    __half2 t = __floats2half2_rn(a, b);
    return *reinterpret_cast<uint32_t*>(&t);
}

// ---------------------------------------------------------------------------
// Single-term fp16 mma.sync GEMM: C[M,N] = A[M,K] @ Bt[N,K]^T
// CTA 128x128, 8 warps (2m x 4n), warp tile 64x32, BK=32, cp.async dbl-buffer.
// SMEM: A @ 0, B @ MOFF; row stride 80B -> conflict-free ldmatrix.
// mode: 1=+bias, 2=relu, 4=+Res, 8=QKV head-major scatter (Q split hi/lo)
// Outputs (nullable): C fp32, Ch fp16; mode8 uses Ch/Cl/K16/V16.
// ---------------------------------------------------------------------------
#define SMS   80
#define MOFF  10240
#define BUFSZ 20480
#define TGSM  (2*BUFSZ)                 // 40960

__global__ __launch_bounds__(256, 1) void tgemm_k(
    const uint4* __restrict__ Ah, const uint4* __restrict__ Bt,
    const float* __restrict__ bias, const float* __restrict__ Res,
    float* __restrict__ C, __half* __restrict__ Ch, __half* __restrict__ Cl,
    __half* __restrict__ K16, __half* __restrict__ V16,
    int M, int N, int K, int mode)
{
    extern __shared__ char sm[];
    const uint32_t sb = smem_u32(sm);
    const int tid  = threadIdx.x;
    const int lane = tid & 31;
    const int warp = tid >> 5;
    const int wm = warp >> 2;
    const int wn = warp & 3;
    const int m0 = blockIdx.x * 128;
    const int n0 = blockIdx.y * 128;

    const int Kv  = K >> 3;
    const int nch = K >> 5;
    const int lrow = tid >> 2;
    const int lseg = tid & 3;

    float acc[4][4][4];
#pragma unroll
    for (int i = 0; i < 4; i++)
#pragma unroll
        for (int j = 0; j < 4; j++)
#pragma unroll
            for (int k = 0; k < 4; k++) acc[i][j][k] = 0.f;

    auto load_chunk = [&](int c) {
        const int b = c & 1;
        const uint32_t base = sb + b * BUFSZ;
        const int kc4 = c << 2;
#pragma unroll
        for (int it = 0; it < 2; it++) {
            int row = lrow + it * 64;
            uint32_t d = base + row * SMS + lseg * 16;
            size_t ga = (size_t)(m0 + row) * Kv + kc4 + lseg;
            CP16(d, Ah + ga);
            int rn = n0 + row; if (rn >= N) rn = N - 1;
            size_t gb = (size_t)rn * Kv + kc4 + lseg;
            CP16(d + MOFF, Bt + gb);
        }
        CP_COMMIT();
    };

    load_chunk(0);

    for (int c = 0; c < nch; c++) {
        if (c + 1 < nch) { load_chunk(c + 1); CP_WAIT1(); }
        else             { CP_WAIT0(); }
        __syncthreads();

        const uint32_t base = sb + (c & 1) * BUFSZ;
        const uint32_t ab = base + (wm * 64 + (lane & 15)) * SMS + ((lane >> 4) << 4);
        const uint32_t bb = base + MOFF + (wn * 32 + (lane & 15)) * SMS + ((lane >> 4) << 4);

#pragma unroll
        for (int ks = 0; ks < 2; ks++) {
            const uint32_t ko = ks << 5;
            uint32_t ahf[16], bf[8];
#pragma unroll
            for (int mt = 0; mt < 4; mt++)
                LDSM4(&ahf[mt*4], ab + mt * (16*SMS) + ko);
#pragma unroll
            for (int q = 0; q < 2; q++)
                LDSM4(&bf[q*4], bb + q * (16*SMS) + ko);
#pragma unroll
            for (int mt = 0; mt < 4; mt++)
#pragma unroll
                for (int nt = 0; nt < 4; nt++) {
                    const int q = (nt >> 1) * 4, r = nt & 1;
                    MMAH(acc[mt][nt], &ahf[mt*4], bf[q+r], bf[q+2+r]);
                }
        }
        __syncthreads();
    }

    // epilogue
#pragma unroll
    for (int mt = 0; mt < 4; mt++) {
        const int row0 = m0 + wm * 64 + mt * 16 + (lane >> 2);
#pragma unroll
        for (int nt = 0; nt < 4; nt++) {
            const int col = n0 + wn * 32 + nt * 8 + ((lane & 3) << 1);
            if (col >= N) continue;
            const float* d = acc[mt][nt];
#pragma unroll
            for (int h = 0; h < 2; h++) {
                const int r = row0 + h * 8;
                size_t o = (size_t)r * N + col;
#pragma unroll
                for (int j = 0; j < 2; j++) {
                    if (col + j >= N) break;
                    float x = d[h*2+j];
                    if (mode & 1) x += bias[col+j];
                    if (mode & 4) x += Res[o+j];
                    if (mode & 2) x = fmaxf(x, 0.f);
                    if (mode & 8) {
                        // head-major scatter: [b][head][s][64]
                        int cc = col + j;
                        int bq = r >> 11, sq = r & 2047;
                        int part = cc / DD;          // 0=Q 1=K 2=V
                        int cd = cc - part * DD;
                        int hd = cd >> 6, dd = cd & 63;
                        size_t oo = (((size_t)(bq*HH + hd))*SS + sq)*64 + dd;
                        if (part == 0)      split_store(x, Ch, Cl, oo);
                        else if (part == 1) K16[oo] = __float2half_rn(x);
                        else                V16[oo] = __float2half_rn(x);
                    } else {
                        if (C)  C[o+j] = x;
                        if (Ch) Ch[o+j] = __float2half_rn(x);
                    }
                }
            }
        }
    }
}

// ---------------------------------------------------------------------------
// PE frequency table:  pebase[d] = 10000^(-2d/D)
// ---------------------------------------------------------------------------
__global__ void pebase_k(float* __restrict__ pb)
{
    int d = blockIdx.x * 256 + threadIdx.x;
    if (d < DD) pb[d] = powf(10000.0f, -2.0f * (float)d / (float)DD);
}

// ---------------------------------------------------------------------------
// Embedding + positional encoding, fused fp16 convert
// ---------------------------------------------------------------------------
__global__ __launch_bounds__(256) void embed_k(const int* __restrict__ ids,
                                               const float* __restrict__ emb,
                                               const float* __restrict__ pb,
                                               float* __restrict__ x,
                                               __half* __restrict__ xh)
{
    int t = blockIdx.x;
    int s = t % SS;
    int id = ids[t];
    const float* er = emb + (size_t)id * DD;
    size_t base = (size_t)t * DD;
    for (int d = threadIdx.x; d < DD; d += 256) {
        float ang = (float)s * pb[d];
        float pe  = (d & 1) ? cosf(ang) : sinf(ang);
        float v = er[d] + pe;
        x[base + d] = v;
        xh[base + d] = __float2half_rn(v);
    }
}

// ---------------------------------------------------------------------------
// Weight transpose + fp16 convert: W[K,N] -> T[N,K]
// ---------------------------------------------------------------------------
__global__ __launch_bounds__(256) void wconvT_k(const float* __restrict__ W,
                                                __half* __restrict__ T,
                                                int K, int N)
{
    __shared__ float t[32][33];
    int k0 = blockIdx.y * 32, n0 = blockIdx.x * 32;
    int tx = threadIdx.x & 31, ty = threadIdx.x >> 5;
#pragma unroll
    for (int i = 0; i < 4; i++) {
        int k = k0 + ty + i * 8, n = n0 + tx;
        t[ty + i * 8][tx] = (k < K && n < N) ? W[(size_t)k * N + n] : 0.f;
    }
    __syncthreads();
#pragma unroll
    for (int i = 0; i < 4; i++) {
        int n = n0 + ty + i * 8, k = k0 + tx;
        if (n < N && k < K)
            T[(size_t)n * K + k] = __float2half_rn(t[tx][ty + i * 8]);
    }
}

// ---------------------------------------------------------------------------
// W_o head-block sum + transpose + fp16
// ---------------------------------------------------------------------------
__global__ __launch_bounds__(256) void wosumT_k(const float* __restrict__ Wo,
                                                __half* __restrict__ T)
{
    __shared__ float t[32][33];
    int r0 = blockIdx.y * 32, c0 = blockIdx.x * 32;
    int tx = threadIdx.x & 31, ty = threadIdx.x >> 5;
#pragma unroll
    for (int i = 0; i < 4; i++) {
        int r = r0 + ty + i * 8;
        float s = 0.f;
#pragma unroll
        for (int h = 0; h < HH; h++)
            s += Wo[((size_t)(h * DD + r)) * DD + c0 + tx];
        t[ty + i * 8][tx] = s;
    }
    __syncthreads();
#pragma unroll
    for (int i = 0; i < 4; i++) {
        int cc = c0 + ty + i * 8;
        int rr = r0 + tx;
        T[(size_t)cc * DD + rr] = __float2half_rn(t[tx][ty + i * 8]);
    }
}

// ---------------------------------------------------------------------------
// Tensor-core causal flash attention (FA2 style).
// grid (S/64, H, B), 128 threads (4 warps x 16 Q rows).
// Q: 2-term fp16 split (exact). K, V, P: single fp16.
// ---------------------------------------------------------------------------
#define SMSA 144
#define ATILE 9216          // 64*144
#define ASM_TOTAL (6*ATILE) // 55296

__global__ __launch_bounds__(128, 1) void attn_k(
    const __half* __restrict__ Qh, const __half* __restrict__ Ql,
    const __half* __restrict__ Kh, const __half* __restrict__ Vh,
    __half* __restrict__ oh)
{
    extern __shared__ char sm[];
    const uint32_t sb = smem_u32(sm);
    const int qb = blockIdx.x, hh = blockIdx.y, bb = blockIdx.z;
    const int tid = threadIdx.x, lane = tid & 31, warp = tid >> 5;
    const size_t hbase = ((size_t)(bb*HH + hh)) * SS * 64;

    const uint32_t sQh = sb;
    const uint32_t sQl = sb + ATILE;
    const uint32_t sK0 = sb + 2*ATILE;
    const uint32_t sV0 = sb + 4*ATILE;

    for (int idx = tid; idx < 512; idx += 128) {
        int r = idx >> 3, seg = idx & 7;
        size_t g = hbase + (size_t)(qb*64 + r)*64 + seg*8;
        CP16(sQh + r*SMSA + seg*16, (const uint4*)(Qh + g));
        CP16(sQl + r*SMSA + seg*16, (const uint4*)(Ql + g));
    }
    CP_COMMIT();

    auto loadKV = [&](int j) {
        uint32_t kb = sK0 + (j & 1)*ATILE;
        uint32_t vb = sV0 + (j & 1)*ATILE;
        for (int idx = tid; idx < 512; idx += 128) {
            int r = idx >> 3, seg = idx & 7;
            size_t g = hbase + (size_t)(j*64 + r)*64 + seg*8;
            CP16(kb + r*SMSA + seg*16, (const uint4*)(Kh + g));
            CP16(vb + r*SMSA + seg*16, (const uint4*)(Vh + g));
        }
        CP_COMMIT();
    };

    loadKV(0);

    uint32_t qfh[4][4], qfl[4][4];
    float oacc[8][4];
    float m[2] = {-1e30f, -1e30f}, l[2] = {0.f, 0.f};
#pragma unroll
    for (int nt = 0; nt < 8; nt++)
#pragma unroll
        for (int j2 = 0; j2 < 4; j2++) oacc[nt][j2] = 0.f;

    const int rowg = lane >> 2;
    const int colg = (lane & 3) << 1;
    const uint32_t aoff = (warp*16 + (lane & 15))*SMSA + ((lane >> 4) << 4);

    for (int j = 0; j <= qb; j++) {
        if (j < qb) loadKV(j + 1);
        if (j < qb) CP_WAIT1(); else CP_WAIT0();
        __syncthreads();

        if (j == 0) {
#pragma unroll
            for (int kk = 0; kk < 4; kk++) {
                LDSM4(qfh[kk], sQh + aoff + kk*32);
                LDSM4(qfl[kk], sQl + aoff + kk*32);
            }
        }

        const uint32_t kb = sK0 + (j & 1)*ATILE;
        const uint32_t vb = sV0 + (j & 1)*ATILE;

        float sacc[8][4];
#pragma unroll
        for (int nt = 0; nt < 8; nt++)
#pragma unroll
            for (int j2 = 0; j2 < 4; j2++) sacc[nt][j2] = 0.f;

#pragma unroll
        for (int kk = 0; kk < 4; kk++) {
            uint32_t bf[16];
#pragma unroll
            for (int q = 0; q < 4; q++)
                LDSM4(&bf[q*4], kb + (q*16 + (lane & 15))*SMSA
                                  + ((lane >> 4) << 4) + kk*32);
#pragma unroll
            for (int nt = 0; nt < 8; nt++) {
                const int q = (nt >> 1)*4, r = nt & 1;
                MMAH(sacc[nt], qfh[kk], bf[q+r], bf[q+2+r]);
                MMAH(sacc[nt], qfl[kk], bf[q+r], bf[q+2+r]);
            }
        }

        const int grow0 = qb*64 + warp*16 + rowg;
#pragma unroll
        for (int nt = 0; nt < 8; nt++)
#pragma unroll
            for (int j2 = 0; j2 < 4; j2++) {
                float s = sacc[nt][j2] * 0.125f;
                if (j == qb) {
                    int gc = j*64 + nt*8 + colg + (j2 & 1);
                    int gr = grow0 + ((j2 >> 1) << 3);
                    if (gc > gr) s = -1e30f;
                }
                sacc[nt][j2] = s;
            }

        float mt[2] = {-1e30f, -1e30f};
#pragma unroll
        for (int nt = 0; nt < 8; nt++) {
            mt[0] = fmaxf(mt[0], fmaxf(sacc[nt][0], sacc[nt][1]));
            mt[1] = fmaxf(mt[1], fmaxf(sacc[nt][2], sacc[nt][3]));
        }
#pragma unroll
        for (int i = 0; i < 2; i++) {
            mt[i] = fmaxf(mt[i], __shfl_xor_sync(0xFFFFFFFFu, mt[i], 1));
            mt[i] = fmaxf(mt[i], __shfl_xor_sync(0xFFFFFFFFu, mt[i], 2));
        }
        float corr[2], mnew[2];
#pragma unroll
        for (int i = 0; i < 2; i++) {
            mnew[i] = fmaxf(m[i], mt[i]);
            corr[i] = __expf(m[i] - mnew[i]);
            m[i] = mnew[i];
        }
        float ls[2] = {0.f, 0.f};
#pragma unroll
        for (int nt = 0; nt < 8; nt++) {
            sacc[nt][0] = __expf(sacc[nt][0] - mnew[0]);
            sacc[nt][1] = __expf(sacc[nt][1] - mnew[0]);
            sacc[nt][2] = __expf(sacc[nt][2] - mnew[1]);
            sacc[nt][3] = __expf(sacc[nt][3] - mnew[1]);
            ls[0] += sacc[nt][0] + sacc[nt][1];
            ls[1] += sacc[nt][2] + sacc[nt][3];
        }
#pragma unroll
        for (int i = 0; i < 2; i++) {
            ls[i] += __shfl_xor_sync(0xFFFFFFFFu, ls[i], 1);
            ls[i] += __shfl_xor_sync(0xFFFFFFFFu, ls[i], 2);
            l[i] = l[i]*corr[i] + ls[i];
        }
#pragma unroll
        for (int nt = 0; nt < 8; nt++) {
            oacc[nt][0] *= corr[0]; oacc[nt][1] *= corr[0];
            oacc[nt][2] *= corr[1]; oacc[nt][3] *= corr[1];
        }

#pragma unroll
        for (int kt = 0; kt < 4; kt++) {
            uint32_t pa[4];
            pa[0] = f22u(sacc[2*kt  ][0], sacc[2*kt  ][1]);
            pa[1] = f22u(sacc[2*kt  ][2], sacc[2*kt  ][3]);
            pa[2] = f22u(sacc[2*kt+1][0], sacc[2*kt+1][1]);
            pa[3] = f22u(sacc[2*kt+1][2], sacc[2*kt+1][3]);
            uint32_t vf[16];
#pragma unroll
            for (int q = 0; q < 4; q++)
                LDSM4T(&vf[q*4], vb + (kt*16 + (lane & 15))*SMSA
                                    + q*32 + ((lane >> 4) << 4));
#pragma unroll
            for (int nt = 0; nt < 8; nt++) {
                const int base = (nt >> 1)*4 + ((nt & 1) << 1);
                MMAH(oacc[nt], pa, vf[base], vf[base+1]);
            }
        }
        __syncthreads();
    }

    float inv[2] = {1.f / l[0], 1.f / l[1]};
#pragma unroll
    for (int nt = 0; nt < 8; nt++)
#pragma unroll
        for (int j2 = 0; j2 < 4; j2++) {
            int srow = qb*64 + warp*16 + rowg + ((j2 >> 1) << 3);
            int tok = bb*SS + srow;
            int col = hh*64 + nt*8 + colg + (j2 & 1);
            oh[(size_t)tok*DD + col] =
                __float2half_rn(oacc[nt][j2] * inv[j2 >> 1]);
        }
}

// ---------------------------------------------------------------------------
// LayerNorm over D=768, optional fp32 out + fp16 out
// ---------------------------------------------------------------------------
__global__ __launch_bounds__(256) void layernorm_k(const float* __restrict__ X,
                                                   const float* __restrict__ g,
                                                   const float* __restrict__ b,
                                                   float* __restrict__ Y,
                                                   __half* __restrict__ Yh)
{
    int t = blockIdx.x;
    const float* xr = X + (size_t)t * DD;
    float vals[3];
    float s = 0.f, s2 = 0.f;
#pragma unroll
    for (int i = 0; i < 3; i++) {
        float v = xr[threadIdx.x + i * 256];
        vals[i] = v;
        s += v; s2 += v * v;
    }
#pragma unroll
    for (int o = 16; o > 0; o >>= 1) {
        s  += __shfl_xor_sync(0xFFFFFFFFu, s,  o);
        s2 += __shfl_xor_sync(0xFFFFFFFFu, s2, o);
    }
    __shared__ float rs[8], rs2[8];
    int w = threadIdx.x >> 5;
    if ((threadIdx.x & 31) == 0) { rs[w] = s; rs2[w] = s2; }
    __syncthreads();
    if (threadIdx.x < 32) {
        s  = (threadIdx.x < 8) ? rs [threadIdx.x] : 0.f;
        s2 = (threadIdx.x < 8) ? rs2[threadIdx.x] : 0.f;
#pragma unroll
        for (int o = 4; o > 0; o >>= 1) {
            s  += __shfl_xor_sync(0xFFFFFFFFu, s,  o);
            s2 += __shfl_xor_sync(0xFFFFFFFFu, s2, o);
        }
        if (threadIdx.x == 0) { rs[0] = s; rs2[0] = s2; }
    }
    __syncthreads();
    float mean = rs[0] * (1.f / DD);
    float var  = rs2[0] * (1.f / DD) - mean * mean;
    float rstd = rsqrtf(var + 1e-5f);
#pragma unroll
    for (int i = 0; i < 3; i++) {
        int d = threadIdx.x + i * 256;
        float v = (vals[i] - mean) * rstd * g[d] + b[d];
        size_t o = (size_t)t * DD + d;
        if (Y)  Y[o] = v;
        Yh[o] = __float2half_rn(v);
    }
}

// ---------------------------------------------------------------------------
// Launch
// ---------------------------------------------------------------------------
static inline void run_gemm(const __half* Ah, const __half* Bt,
                            const float* bias, const float* Res,
                            float* C, __half* Ch, __half* Cl,
                            __half* K16, __half* V16,
                            int M, int N, int K, int mode)
{
    dim3 grid(M / 128, (N + 127) / 128);
    tgemm_k<<<grid, 256, TGSM>>>((const uint4*)Ah, (const uint4*)Bt,
                                 bias, Res, C, Ch, Cl, K16, V16,
                                 M, N, K, mode);
}

extern "C" void kernel_launch(void* const* d_in, const int* in_sizes, int n_in,
                              void* d_out, int out_size)
{
    const int*   ids    = (const int*)  d_in[0];
    const float* emb    = (const float*)d_in[1];
    const float* W_qkv  = (const float*)d_in[2];
    const float* b_qkv  = (const float*)d_in[3];
    const float* W_o    = (const float*)d_in[4];
    const float* b_o    = (const float*)d_in[5];
    const float* ln1_g  = (const float*)d_in[6];
    const float* ln1_b  = (const float*)d_in[7];
    const float* W_ff1  = (const float*)d_in[8];
    const float* b_ff1  = (const float*)d_in[9];
    const float* W_ff2  = (const float*)d_in[10];
    const float* b_ff2  = (const float*)d_in[11];
    const float* ln2_g  = (const float*)d_in[12];
    const float* ln2_b  = (const float*)d_in[13];
    const float* W_out  = (const float*)d_in[14];
    const float* b_out  = (const float*)d_in[15];
    float* out = (float*)d_out;

    cudaFuncSetAttribute(tgemm_k, cudaFuncAttributeMaxDynamicSharedMemorySize, TGSM);
    cudaFuncSetAttribute(attn_k, cudaFuncAttributeMaxDynamicSharedMemorySize, ASM_TOTAL);

    float *px, *pmha, *ph1, *pffo, *ppb;
    cudaGetSymbolAddress((void**)&px,   g_x);
    cudaGetSymbolAddress((void**)&pmha, g_mha);
    cudaGetSymbolAddress((void**)&ph1,  g_h1);
    cudaGetSymbolAddress((void**)&pffo, g_ffo);
    cudaGetSymbolAddress((void**)&ppb,  g_pebase);

    __half *xh,*ath,*h1h,*ffh,*h2h;
    cudaGetSymbolAddress((void**)&xh,  g_xh);
    cudaGetSymbolAddress((void**)&ath, g_ath);
    cudaGetSymbolAddress((void**)&h1h, g_h1h);
    cudaGetSymbolAddress((void**)&ffh, g_ffh);
    cudaGetSymbolAddress((void**)&h2h, g_h2h);

    __half *qh,*ql,*kh,*vh;
    cudaGetSymbolAddress((void**)&qh, g_qh); cudaGetSymbolAddress((void**)&ql, g_ql);
    cudaGetSymbolAddress((void**)&kh, g_kh); cudaGetSymbolAddress((void**)&vh, g_vh);

    __half *wq,*ws,*w1,*w2,*wo;
    cudaGetSymbolAddress((void**)&wq, g_wqkvT);
    cudaGetSymbolAddress((void**)&ws, g_wsumT);
    cudaGetSymbolAddress((void**)&w1, g_wff1T);
    cudaGetSymbolAddress((void**)&w2, g_wff2T);
    cudaGetSymbolAddress((void**)&wo, g_woutT);

    // Weight prep
    wconvT_k<<<dim3((3*DD + 31)/32, (DD + 31)/32), 256>>>(W_qkv, wq, DD, 3*DD);
    wosumT_k<<<dim3(DD/32, DD/32), 256>>>(W_o, ws);
    wconvT_k<<<dim3((FFD + 31)/32, (DD + 31)/32), 256>>>(W_ff1, w1, DD, FFD);
    wconvT_k<<<dim3((DD + 31)/32, (FFD + 31)/32), 256>>>(W_ff2, w2, FFD, DD);
    wconvT_k<<<dim3((VV + 31)/32, (DD + 31)/32), 256>>>(W_out, wo, DD, VV);

    // 1. embeddings + PE
    pebase_k<<<3, 256>>>(ppb);
    embed_k<<<NTOK, 256>>>(ids, emb, ppb, px, xh);

    // 2. QKV projection -> head-major fp16 Q(hi/lo), K, V
    run_gemm(xh, wq, b_qkv, nullptr,
             nullptr, qh, ql, kh, vh,
             NTOK, 3*DD, DD, 1|8);

    // 3. tensor-core flash attention
    attn_k<<<dim3(SS/64, HH, BB), 128, ASM_TOTAL>>>(qh, ql, kh, vh, ath);

    // 4. mha = attn @ Wsum + b_o + x  (fp32 residual add in epilogue)
    run_gemm(ath, ws, b_o, px,
             pmha, nullptr, nullptr, nullptr, nullptr,
             NTOK, DD, DD, 1|4);

    // 5. LN1 (fp32 residual + fp16 out)
    layernorm_k<<<NTOK, 256>>>(pmha, ln1_g, ln1_b, ph1, h1h);

    // 6. FF1 + relu (fp16 out)
    run_gemm(h1h, w1, b_ff1, nullptr,
             nullptr, ffh, nullptr, nullptr, nullptr,
             NTOK, FFD, DD, 1|2);

    // 7. FF2 + residual (fp32 out)
    run_gemm(ffh, w2, b_ff2, ph1,
             pffo, nullptr, nullptr, nullptr, nullptr,
             NTOK, DD, FFD, 1|4);

    // 8. LN2 (fp16 out)
    layernorm_k<<<NTOK, 256>>>(pffo, ln2_g, ln2_b, nullptr, h2h);

    // 9. vocab projection
    run_gemm(h2h, wo, b_out, nullptr,
             out, nullptr, nullptr, nullptr, nullptr,
             NTOK, VV, DD, 1);
}

// round 9
// speedup vs baseline: 6.2119x; 1.0115x over previous
#include <cuda_runtime.h>
#include <cuda_fp16.h>
#include <math.h>
#include <stdint.h>

// Problem constants
#define BB   2
#define SS   2048
#define DD   768
#define HH   12
#define VV   50257
#define FFD  3072
#define HDIM 64
#define NTOK (BB*SS)

// ---------------------------------------------------------------------------
// Scratch (static device globals -- no allocation allowed)
// ---------------------------------------------------------------------------
__device__ float g_x   [NTOK*DD];      // embeddings + PE (residual for step 4)
__device__ float g_mha [NTOK*DD];
__device__ float g_h1  [NTOK*DD];      // LN1 out fp32 (residual for step 7)
__device__ float g_ffo [NTOK*DD];
__device__ float g_pebase[DD];         // 10000^(-2d/D)

// fp16 activations (A operands, single-term)
__device__ __half g_xh [NTOK*DD];
__device__ __half g_ath[NTOK*DD];
__device__ __half g_h1h[NTOK*DD];
__device__ __half g_ffh[NTOK*FFD];
__device__ __half g_h2h[NTOK*DD];

// head-major attention operands [b][h][s][64]
__device__ __half g_qh[NTOK*DD];
__device__ __half g_kh[NTOK*DD];
__device__ __half g_vh[NTOK*DD];

// fp16 transposed weights [N,K]
__device__ __half g_wqkvT[3*DD*DD];
__device__ __half g_wsumT[DD*DD];
__device__ __half g_wff1T[(size_t)FFD*DD];
__device__ __half g_wff2T[(size_t)DD*FFD];
__device__ __half g_woutT[(size_t)VV*DD];

// ---------------------------------------------------------------------------
// PTX helpers (plain sm_103-safe: cp.async, ldmatrix, mma.sync only)
// ---------------------------------------------------------------------------
__device__ __forceinline__ uint32_t smem_u32(const void* p) {
    uint32_t a;
    asm("{ .reg .u64 t; cvta.to.shared.u64 t, %1; cvt.u32.u64 %0, t; }"
        : "=r"(a) : "l"(p));
    return a;
}

#define CP16(dst, src) \
    asm volatile("cp.async.cg.shared.global [%0], [%1], 16;" \
                 :: "r"(dst), "l"(src) : "memory")
#define CP_COMMIT() asm volatile("cp.async.commit_group;" ::: "memory")
#define CP_WAIT1()  asm volatile("cp.async.wait_group 1;"  ::: "memory")
#define CP_WAIT0()  asm volatile("cp.async.wait_group 0;"  ::: "memory")

#define LDSM4(r, a) \
    asm volatile("ldmatrix.sync.aligned.m8n8.x4.shared.b16 {%0,%1,%2,%3}, [%4];" \
        : "=r"((r)[0]), "=r"((r)[1]), "=r"((r)[2]), "=r"((r)[3]) : "r"(a))

#define LDSM4T(r, a) \
    asm volatile("ldmatrix.sync.aligned.m8n8.x4.trans.shared.b16 {%0,%1,%2,%3}, [%4];" \
        : "=r"((r)[0]), "=r"((r)[1]), "=r"((r)[2]), "=r"((r)[3]) : "r"(a))

#define MMAH(d, a, b0, b1) \
    asm volatile("mma.sync.aligned.m16n8k16.row.col.f32.f16.f16.f32 " \
        "{%0,%1,%2,%3}, {%4,%5,%6,%7}, {%8,%9}, {%0,%1,%2,%3};" \
        : "+f"((d)[0]), "+f"((d)[1]), "+f"((d)[2]), "+f"((d)[3]) \
        : "r"((a)[0]), "r"((a)[1]), "r"((a)[2]), "r"((a)[3]), \
          "r"(b0), "r"(b1))

__device__ __forceinline__ uint32_t f22u(float a, float b) {
    __half2 t = __floats2half2_rn(a, b);
    return *reinterpret_cast<uint32_t*>(&t);
}

// ---------------------------------------------------------------------------
// Single-term fp16 mma.sync GEMM: C[M,N] = A[M,K] @ Bt[N,K]^T
// Template MT = per-warp m-subtiles (4 -> CTA 128xN, 2 -> CTA 64xN).
// 8 warps (2m x 4n), warp tile (16*MT)x32, BK=32, cp.async double-buffer.
// SMEM row stride 80B -> conflict-free ldmatrix.
// mode: 1=+bias, 2=relu, 4=+Res, 8=QKV head-major scatter
// ---------------------------------------------------------------------------
#define SMS 80

template<int MT>
__global__ __launch_bounds__(256, 1) void tgemm_k(
    const uint4* __restrict__ Ah, const uint4* __restrict__ Bt,
    const float* __restrict__ bias, const float* __restrict__ Res,
    float* __restrict__ C, __half* __restrict__ Ch,
    __half* __restrict__ K16, __half* __restrict__ V16,
    int M, int N, int K, int mode)
{
    constexpr int ABY = 32*MT*SMS;       // A tile bytes
    constexpr int BUF = ABY + 128*SMS;   // A + B per buffer

    extern __shared__ char sm[];
    const uint32_t sb = smem_u32(sm);
    const int tid  = threadIdx.x;
    const int lane = tid & 31;
    const int warp = tid >> 5;
    const int wm = warp >> 2;
    const int wn = warp & 3;
    const int m0 = blockIdx.x * (32*MT);
    const int n0 = blockIdx.y * 128;

    const int Kv  = K >> 3;
    const int nch = K >> 5;
    const int lrow = tid >> 2;
    const int lseg = tid & 3;

    float acc[MT][4][4];
#pragma unroll
    for (int i = 0; i < MT; i++)
#pragma unroll
        for (int j = 0; j < 4; j++)
#pragma unroll
            for (int k = 0; k < 4; k++) acc[i][j][k] = 0.f;

    auto load_chunk = [&](int c) {
        const int b = c & 1;
        const uint32_t base = sb + b * BUF;
        const int kc4 = c << 2;
#pragma unroll
        for (int it = 0; it < MT/2; it++) {
            int row = lrow + it * 64;
            size_t ga = (size_t)(m0 + row) * Kv + kc4 + lseg;
            CP16(base + row * SMS + lseg * 16, Ah + ga);
        }
#pragma unroll
        for (int it = 0; it < 2; it++) {
            int row = lrow + it * 64;
            int rn = n0 + row; if (rn >= N) rn = N - 1;
            size_t gb = (size_t)rn * Kv + kc4 + lseg;
            CP16(base + ABY + row * SMS + lseg * 16, Bt + gb);
        }
        CP_COMMIT();
    };

    load_chunk(0);

    for (int c = 0; c < nch; c++) {
        if (c + 1 < nch) { load_chunk(c + 1); CP_WAIT1(); }
        else             { CP_WAIT0(); }
        __syncthreads();

        const uint32_t base = sb + (c & 1) * BUF;
        const uint32_t ab = base + (wm * (16*MT) + (lane & 15)) * SMS + ((lane >> 4) << 4);
        const uint32_t bb = base + ABY + (wn * 32 + (lane & 15)) * SMS + ((lane >> 4) << 4);

#pragma unroll
        for (int ks = 0; ks < 2; ks++) {
            const uint32_t ko = ks << 5;
            uint32_t ahf[MT*4], bf[8];
#pragma unroll
            for (int mt = 0; mt < MT; mt++)
                LDSM4(&ahf[mt*4], ab + mt * (16*SMS) + ko);
#pragma unroll
            for (int q = 0; q < 2; q++)
                LDSM4(&bf[q*4], bb + q * (16*SMS) + ko);
#pragma unroll
            for (int mt = 0; mt < MT; mt++)
#pragma unroll
                for (int nt = 0; nt < 4; nt++) {
                    const int q = (nt >> 1) * 4, r = nt & 1;
                    MMAH(acc[mt][nt], &ahf[mt*4], bf[q+r], bf[q+2+r]);
                }
        }
        __syncthreads();
    }

    // epilogue
#pragma unroll
    for (int mt = 0; mt < MT; mt++) {
        const int row0 = m0 + wm * (16*MT) + mt * 16 + (lane >> 2);
#pragma unroll
        for (int nt = 0; nt < 4; nt++) {
            const int col = n0 + wn * 32 + nt * 8 + ((lane & 3) << 1);
            if (col >= N) continue;
            const float* d = acc[mt][nt];
#pragma unroll
            for (int h = 0; h < 2; h++) {
                const int r = row0 + h * 8;
                size_t o = (size_t)r * N + col;
#pragma unroll
                for (int j = 0; j < 2; j++) {
                    if (col + j >= N) break;
                    float x = d[h*2+j];
                    if (mode & 1) x += bias[col+j];
                    if (mode & 4) x += Res[o+j];
                    if (mode & 2) x = fmaxf(x, 0.f);
                    if (mode & 8) {
                        // head-major scatter: [b][head][s][64]
                        int cc = col + j;
                        int bq = r >> 11, sq = r & 2047;
                        int part = cc / DD;          // 0=Q 1=K 2=V
                        int cd = cc - part * DD;
                        int hd = cd >> 6, dd = cd & 63;
                        size_t oo = (((size_t)(bq*HH + hd))*SS + sq)*64 + dd;
                        __half hv = __float2half_rn(x);
                        if (part == 0)      Ch[oo]  = hv;
                        else if (part == 1) K16[oo] = hv;
                        else                V16[oo] = hv;
                    } else {
                        if (C)  C[o+j] = x;
                        if (Ch) Ch[o+j] = __float2half_rn(x);
                    }
                }
            }
        }
    }
}

// ---------------------------------------------------------------------------
// PE frequency table:  pebase[d] = 10000^(-2d/D)
// ---------------------------------------------------------------------------
__global__ void pebase_k(float* __restrict__ pb)
{
    int d = blockIdx.x * 256 + threadIdx.x;
    if (d < DD) pb[d] = powf(10000.0f, -2.0f * (float)d / (float)DD);
}

// ---------------------------------------------------------------------------
// Embedding + positional encoding, fused fp16 convert
// ---------------------------------------------------------------------------
__global__ __launch_bounds__(256) void embed_k(const int* __restrict__ ids,
                                               const float* __restrict__ emb,
                                               const float* __restrict__ pb,
                                               float* __restrict__ x,
                                               __half* __restrict__ xh)
{
    int t = blockIdx.x;
    int s = t % SS;
    int id = ids[t];
    const float* er = emb + (size_t)id * DD;
    size_t base = (size_t)t * DD;
    for (int d = threadIdx.x; d < DD; d += 256) {
        float ang = (float)s * pb[d];
        float pe  = (d & 1) ? cosf(ang) : sinf(ang);
        float v = er[d] + pe;
        x[base + d] = v;
        xh[base + d] = __float2half_rn(v);
    }
}

// ---------------------------------------------------------------------------
// Weight transpose + fp16 convert: W[K,N] -> T[N,K]
// 32(k) x 64(n) tiles, [32][65] stage (conflict-free), 8B vector stores.
// Requires K % 32 == 0 (all our K: 768, 3072).
// ---------------------------------------------------------------------------
__global__ __launch_bounds__(256) void wconvT_k(const float* __restrict__ W,
                                                __half* __restrict__ T,
                                                int K, int N)
{
    __shared__ float t[32][65];
    int k0 = blockIdx.y * 32, n0 = blockIdx.x * 64;

    for (int i = threadIdx.x; i < 2048; i += 256) {
        int r = i >> 6, c = i & 63;
        int n = n0 + c;
        t[r][c] = (n < N) ? W[(size_t)(k0 + r) * N + n] : 0.f;
    }
    __syncthreads();

    for (int i = threadIdx.x; i < 512; i += 256) {
        int n = i >> 3, kc = (i & 7) << 2;
        if (n0 + n >= N) continue;
        __half h[4];
#pragma unroll
        for (int j = 0; j < 4; j++) h[j] = __float2half_rn(t[kc + j][n]);
        *(uint2*)&T[(size_t)(n0 + n) * K + k0 + kc] = *(uint2*)h;
    }
}

// ---------------------------------------------------------------------------
// W_o head-block sum + transpose + fp16
// ---------------------------------------------------------------------------
__global__ __launch_bounds__(256) void wosumT_k(const float* __restrict__ Wo,
                                                __half* __restrict__ T)
{
    __shared__ float t[32][33];
    int r0 = blockIdx.y * 32, c0 = blockIdx.x * 32;
    int tx = threadIdx.x & 31, ty = threadIdx.x >> 5;
#pragma unroll
    for (int i = 0; i < 4; i++) {
        int r = r0 + ty + i * 8;
        float s = 0.f;
#pragma unroll
        for (int h = 0; h < HH; h++)
            s += Wo[((size_t)(h * DD + r)) * DD + c0 + tx];
        t[ty + i * 8][tx] = s;
    }
    __syncthreads();
#pragma unroll
    for (int i = 0; i < 4; i++) {
        int cc = c0 + ty + i * 8;
        int rr = r0 + tx;
        T[(size_t)cc * DD + rr] = __float2half_rn(t[tx][ty + i * 8]);
    }
}

// ---------------------------------------------------------------------------
// Tensor-core causal flash attention (FA2 style), single-term fp16 Q/K/V/P.
// grid (S/64, H, B), 128 threads (4 warps x 16 Q rows).
// Heavy-tile-first: qb = gridDim.x-1-blockIdx.x.
// ---------------------------------------------------------------------------
#define SMSA 144
#define ATILE 9216          // 64*144
#define ASM_TOTAL (5*ATILE) // 46080  (Q, K x2, V x2)

__global__ __launch_bounds__(128, 1) void attn_k(
    const __half* __restrict__ Qh,
    const __half* __restrict__ Kh, const __half* __restrict__ Vh,
    __half* __restrict__ oh)
{
    extern __shared__ char sm[];
    const uint32_t sb = smem_u32(sm);
    const int qb = gridDim.x - 1 - blockIdx.x;   // heavy tiles first
    const int hh = blockIdx.y, bb = blockIdx.z;
    const int tid = threadIdx.x, lane = tid & 31, warp = tid >> 5;
    const size_t hbase = ((size_t)(bb*HH + hh)) * SS * 64;

    const uint32_t sQ  = sb;
    const uint32_t sK0 = sb + ATILE;
    const uint32_t sV0 = sb + 3*ATILE;

    for (int idx = tid; idx < 512; idx += 128) {
        int r = idx >> 3, seg = idx & 7;
        size_t g = hbase + (size_t)(qb*64 + r)*64 + seg*8;
        CP16(sQ + r*SMSA + seg*16, (const uint4*)(Qh + g));
    }
    CP_COMMIT();

    auto loadKV = [&](int j) {
        uint32_t kb = sK0 + (j & 1)*ATILE;
        uint32_t vb = sV0 + (j & 1)*ATILE;
        for (int idx = tid; idx < 512; idx += 128) {
            int r = idx >> 3, seg = idx & 7;
            size_t g = hbase + (size_t)(j*64 + r)*64 + seg*8;
            CP16(kb + r*SMSA + seg*16, (const uint4*)(Kh + g));
            CP16(vb + r*SMSA + seg*16, (const uint4*)(Vh + g));
        }
        CP_COMMIT();
    };

    loadKV(0);

    uint32_t qf[4][4];
    float oacc[8][4];
    float m[2] = {-1e30f, -1e30f}, l[2] = {0.f, 0.f};
#pragma unroll
    for (int nt = 0; nt < 8; nt++)
#pragma unroll
        for (int j2 = 0; j2 < 4; j2++) oacc[nt][j2] = 0.f;

    const int rowg = lane >> 2;
    const int colg = (lane & 3) << 1;
    const uint32_t aoff = (warp*16 + (lane & 15))*SMSA + ((lane >> 4) << 4);

    for (int j = 0; j <= qb; j++) {
        if (j < qb) loadKV(j + 1);
        if (j < qb) CP_WAIT1(); else CP_WAIT0();
        __syncthreads();

        if (j == 0) {
#pragma unroll
            for (int kk = 0; kk < 4; kk++)
                LDSM4(qf[kk], sQ + aoff + kk*32);
        }

        const uint32_t kb = sK0 + (j & 1)*ATILE;
        const uint32_t vb = sV0 + (j & 1)*ATILE;

        float sacc[8][4];
#pragma unroll
        for (int nt = 0; nt < 8; nt++)
#pragma unroll
            for (int j2 = 0; j2 < 4; j2++) sacc[nt][j2] = 0.f;

#pragma unroll
        for (int kk = 0; kk < 4; kk++) {
            uint32_t bf[16];
#pragma unroll
            for (int q = 0; q < 4; q++)
                LDSM4(&bf[q*4], kb + (q*16 + (lane & 15))*SMSA
                                  + ((lane >> 4) << 4) + kk*32);
#pragma unroll
            for (int nt = 0; nt < 8; nt++) {
                const int q = (nt >> 1)*4, r = nt & 1;
                MMAH(sacc[nt], qf[kk], bf[q+r], bf[q+2+r]);
            }
        }

        const int grow0 = qb*64 + warp*16 + rowg;
#pragma unroll
        for (int nt = 0; nt < 8; nt++)
#pragma unroll
            for (int j2 = 0; j2 < 4; j2++) {
                float s = sacc[nt][j2] * 0.125f;
                if (j == qb) {
                    int gc = j*64 + nt*8 + colg + (j2 & 1);
                    int gr = grow0 + ((j2 >> 1) << 3);
                    if (gc > gr) s = -1e30f;
                }
                sacc[nt][j2] = s;
            }

        float mt[2] = {-1e30f, -1e30f};
#pragma unroll
        for (int nt = 0; nt < 8; nt++) {
            mt[0] = fmaxf(mt[0], fmaxf(sacc[nt][0], sacc[nt][1]));
            mt[1] = fmaxf(mt[1], fmaxf(sacc[nt][2], sacc[nt][3]));
        }
#pragma unroll
        for (int i = 0; i < 2; i++) {
            mt[i] = fmaxf(mt[i], __shfl_xor_sync(0xFFFFFFFFu, mt[i], 1));
            mt[i] = fmaxf(mt[i], __shfl_xor_sync(0xFFFFFFFFu, mt[i], 2));
        }
        float corr[2], mnew[2];
#pragma unroll
        for (int i = 0; i < 2; i++) {
            mnew[i] = fmaxf(m[i], mt[i]);
            corr[i] = __expf(m[i] - mnew[i]);
            m[i] = mnew[i];
        }
        float ls[2] = {0.f, 0.f};
#pragma unroll
        for (int nt = 0; nt < 8; nt++) {
            sacc[nt][0] = __expf(sacc[nt][0] - mnew[0]);
            sacc[nt][1] = __expf(sacc[nt][1] - mnew[0]);
            sacc[nt][2] = __expf(sacc[nt][2] - mnew[1]);
            sacc[nt][3] = __expf(sacc[nt][3] - mnew[1]);
            ls[0] += sacc[nt][0] + sacc[nt][1];
            ls[1] += sacc[nt][2] + sacc[nt][3];
        }
#pragma unroll
        for (int i = 0; i < 2; i++) {
            ls[i] += __shfl_xor_sync(0xFFFFFFFFu, ls[i], 1);
            ls[i] += __shfl_xor_sync(0xFFFFFFFFu, ls[i], 2);
            l[i] = l[i]*corr[i] + ls[i];
        }
#pragma unroll
        for (int nt = 0; nt < 8; nt++) {
            oacc[nt][0] *= corr[0]; oacc[nt][1] *= corr[0];
            oacc[nt][2] *= corr[1]; oacc[nt][3] *= corr[1];
        }

#pragma unroll
        for (int kt = 0; kt < 4; kt++) {
            uint32_t pa[4];
            pa[0] = f22u(sacc[2*kt  ][0], sacc[2*kt  ][1]);
            pa[1] = f22u(sacc[2*kt  ][2], sacc[2*kt  ][3]);
            pa[2] = f22u(sacc[2*kt+1][0], sacc[2*kt+1][1]);
            pa[3] = f22u(sacc[2*kt+1][2], sacc[2*kt+1][3]);
            uint32_t vf[16];
#pragma unroll
            for (int q = 0; q < 4; q++)
                LDSM4T(&vf[q*4], vb + (kt*16 + (lane & 15))*SMSA
                                    + q*32 + ((lane >> 4) << 4));
#pragma unroll
            for (int nt = 0; nt < 8; nt++) {
                const int base = (nt >> 1)*4 + ((nt & 1) << 1);
                MMAH(oacc[nt], pa, vf[base], vf[base+1]);
            }
        }
        __syncthreads();
    }

    float inv[2] = {1.f / l[0], 1.f / l[1]};
#pragma unroll
    for (int nt = 0; nt < 8; nt++)
#pragma unroll
        for (int j2 = 0; j2 < 4; j2++) {
            int srow = qb*64 + warp*16 + rowg + ((j2 >> 1) << 3);
            int tok = bb*SS + srow;
            int col = hh*64 + nt*8 + colg + (j2 & 1);
            oh[(size_t)tok*DD + col] =
                __float2half_rn(oacc[nt][j2] * inv[j2 >> 1]);
        }
}

// ---------------------------------------------------------------------------
// LayerNorm over D=768, optional fp32 out + fp16 out
// ---------------------------------------------------------------------------
__global__ __launch_bounds__(256) void layernorm_k(const float* __restrict__ X,
                                                   const float* __restrict__ g,
                                                   const float* __restrict__ b,
                                                   float* __restrict__ Y,
                                                   __half* __restrict__ Yh)
{
    int t = blockIdx.x;
    const float* xr = X + (size_t)t * DD;
    float vals[3];
    float s = 0.f, s2 = 0.f;
#pragma unroll
    for (int i = 0; i < 3; i++) {
        float v = xr[threadIdx.x + i * 256];
        vals[i] = v;
        s += v; s2 += v * v;
    }
#pragma unroll
    for (int o = 16; o > 0; o >>= 1) {
        s  += __shfl_xor_sync(0xFFFFFFFFu, s,  o);
        s2 += __shfl_xor_sync(0xFFFFFFFFu, s2, o);
    }
    __shared__ float rs[8], rs2[8];
    int w = threadIdx.x >> 5;
    if ((threadIdx.x & 31) == 0) { rs[w] = s; rs2[w] = s2; }
    __syncthreads();
    if (threadIdx.x < 32) {
        s  = (threadIdx.x < 8) ? rs [threadIdx.x] : 0.f;
        s2 = (threadIdx.x < 8) ? rs2[threadIdx.x] : 0.f;
#pragma unroll
        for (int o = 4; o > 0; o >>= 1) {
            s  += __shfl_xor_sync(0xFFFFFFFFu, s,  o);
            s2 += __shfl_xor_sync(0xFFFFFFFFu, s2, o);
        }
        if (threadIdx.x == 0) { rs[0] = s; rs2[0] = s2; }
    }
    __syncthreads();
    float mean = rs[0] * (1.f / DD);
    float var  = rs2[0] * (1.f / DD) - mean * mean;
    float rstd = rsqrtf(var + 1e-5f);
#pragma unroll
    for (int i = 0; i < 3; i++) {
        int d = threadIdx.x + i * 256;
        float v = (vals[i] - mean) * rstd * g[d] + b[d];
        size_t o = (size_t)t * DD + d;
        if (Y)  Y[o] = v;
        Yh[o] = __float2half_rn(v);
    }
}

// ---------------------------------------------------------------------------
// Launch
// ---------------------------------------------------------------------------
template<int MT>
static inline void run_gemm(const __half* Ah, const __half* Bt,
                            const float* bias, const float* Res,
                            float* C, __half* Ch, __half* K16, __half* V16,
                            int M, int N, int K, int mode)
{
    dim3 grid(M / (32*MT), (N + 127) / 128);
    int smem = 2 * (32*MT*SMS + 128*SMS);
    tgemm_k<MT><<<grid, 256, smem>>>((const uint4*)Ah, (const uint4*)Bt,
                                     bias, Res, C, Ch, K16, V16,
                                     M, N, K, mode);
}

extern "C" void kernel_launch(void* const* d_in, const int* in_sizes, int n_in,
                              void* d_out, int out_size)
{
    const int*   ids    = (const int*)  d_in[0];
    const float* emb    = (const float*)d_in[1];
    const float* W_qkv  = (const float*)d_in[2];
    const float* b_qkv  = (const float*)d_in[3];
    const float* W_o    = (const float*)d_in[4];
    const float* b_o    = (const float*)d_in[5];
    const float* ln1_g  = (const float*)d_in[6];
    const float* ln1_b  = (const float*)d_in[7];
    const float* W_ff1  = (const float*)d_in[8];
    const float* b_ff1  = (const float*)d_in[9];
    const float* W_ff2  = (const float*)d_in[10];
    const float* b_ff2  = (const float*)d_in[11];
    const float* ln2_g  = (const float*)d_in[12];
    const float* ln2_b  = (const float*)d_in[13];
    const float* W_out  = (const float*)d_in[14];
    const float* b_out  = (const float*)d_in[15];
    float* out = (float*)d_out;

    cudaFuncSetAttribute(tgemm_k<4>, cudaFuncAttributeMaxDynamicSharedMemorySize,
                         2*(128*SMS + 128*SMS));
    cudaFuncSetAttribute(tgemm_k<2>, cudaFuncAttributeMaxDynamicSharedMemorySize,
                         2*(64*SMS + 128*SMS));
    cudaFuncSetAttribute(attn_k, cudaFuncAttributeMaxDynamicSharedMemorySize,
                         ASM_TOTAL);

    float *px, *pmha, *ph1, *pffo, *ppb;
    cudaGetSymbolAddress((void**)&px,   g_x);
    cudaGetSymbolAddress((void**)&pmha, g_mha);
    cudaGetSymbolAddress((void**)&ph1,  g_h1);
    cudaGetSymbolAddress((void**)&pffo, g_ffo);
    cudaGetSymbolAddress((void**)&ppb,  g_pebase);

    __half *xh,*ath,*h1h,*ffh,*h2h;
    cudaGetSymbolAddress((void**)&xh,  g_xh);
    cudaGetSymbolAddress((void**)&ath, g_ath);
    cudaGetSymbolAddress((void**)&h1h, g_h1h);
    cudaGetSymbolAddress((void**)&ffh, g_ffh);
    cudaGetSymbolAddress((void**)&h2h, g_h2h);

    __half *qh,*kh,*vh;
    cudaGetSymbolAddress((void**)&qh, g_qh);
    cudaGetSymbolAddress((void**)&kh, g_kh);
    cudaGetSymbolAddress((void**)&vh, g_vh);

    __half *wq,*ws,*w1,*w2,*wo;
    cudaGetSymbolAddress((void**)&wq, g_wqkvT);
    cudaGetSymbolAddress((void**)&ws, g_wsumT);
    cudaGetSymbolAddress((void**)&w1, g_wff1T);
    cudaGetSymbolAddress((void**)&w2, g_wff2T);
    cudaGetSymbolAddress((void**)&wo, g_woutT);

    // Weight prep (K % 32 == 0 for all)
    wconvT_k<<<dim3((3*DD + 63)/64, DD/32), 256>>>(W_qkv, wq, DD, 3*DD);
    wosumT_k<<<dim3(DD/32, DD/32), 256>>>(W_o, ws);
    wconvT_k<<<dim3((FFD + 63)/64, DD/32), 256>>>(W_ff1, w1, DD, FFD);
    wconvT_k<<<dim3((DD + 63)/64, FFD/32), 256>>>(W_ff2, w2, FFD, DD);
    wconvT_k<<<dim3((VV + 63)/64, DD/32), 256>>>(W_out, wo, DD, VV);

    // 1. embeddings + PE
    pebase_k<<<3, 256>>>(ppb);
    embed_k<<<NTOK, 256>>>(ids, emb, ppb, px, xh);

    // 2. QKV projection -> head-major fp16 Q, K, V
    run_gemm<4>(xh, wq, b_qkv, nullptr,
                nullptr, qh, kh, vh,
                NTOK, 3*DD, DD, 1|8);

    // 3. tensor-core flash attention (heavy-first scheduling)
    attn_k<<<dim3(SS/64, HH, BB), 128, ASM_TOTAL>>>(qh, kh, vh, ath);

    // 4. mha = attn @ Wsum + b_o + x  (M64 tiles: N=768 -> better waves)
    run_gemm<2>(ath, ws, b_o, px,
                pmha, nullptr, nullptr, nullptr,
                NTOK, DD, DD, 1|4);

    // 5. LN1 (fp32 residual + fp16 out)
    layernorm_k<<<NTOK, 256>>>(pmha, ln1_g, ln1_b, ph1, h1h);

    // 6. FF1 + relu (fp16 out)
    run_gemm<4>(h1h, w1, b_ff1, nullptr,
                nullptr, ffh, nullptr, nullptr,
                NTOK, FFD, DD, 1|2);

    // 7. FF2 + residual (fp32 out; M64 tiles for N=768)
    run_gemm<2>(ffh, w2, b_ff2, ph1,
                pffo, nullptr, nullptr, nullptr,
                NTOK, DD, FFD, 1|4);

    // 8. LN2 (fp16 out)
    layernorm_k<<<NTOK, 256>>>(pffo, ln2_g, ln2_b, nullptr, h2h);

    // 9. vocab projection
    run_gemm<4>(h2h, wo, b_out, nullptr,
                out, nullptr, nullptr, nullptr,
                NTOK, VV, DD, 1);
}